// round 6
// baseline (speedup 1.0000x reference)
#include <cuda_runtime.h>
#include <cuda_bf16.h>

// Problem constants (fixed shapes)
#define T_TOK 2304
#define NB    2
#define CIN   256
#define C4    64
#define NS    4
#define NH    4
#define DH    64
#define HH    48
#define WW    48

// ---------------- scratch (device globals; no allocation allowed) ----------
__device__ __align__(128) float g_identity[NB * T_TOK * CIN];
__device__ __align__(128) float g_R[NS * NB * T_TOK * C4];
__device__ __align__(128) float g_V[NS * NB * T_TOK * CIN];
__device__ __align__(128) float g_O[NB * T_TOK * 4 * CIN];
__device__ __align__(128) float g_bn1s[CIN], g_bn1bb[CIN];
__device__ __align__(128) float g_bn2s[C4],  g_bn2bb[C4];
#define NPAIR (NS * NB * T_TOK * (CIN / 2))
__device__ __align__(128) unsigned g_Qh[NPAIR], g_Ql[NPAIR];
__device__ __align__(128) unsigned g_Kh[NPAIR], g_Kl[NPAIR];
__device__ __align__(128) unsigned g_VTh[NPAIR], g_VTl[NPAIR];

// ---------------- BN folding ----------------------------------------------
__global__ void bn_prep_kernel(const float* __restrict__ g, const float* __restrict__ b,
                               const float* __restrict__ m, const float* __restrict__ v,
                               float* __restrict__ s, float* __restrict__ o, int n)
{
    int i = blockIdx.x * blockDim.x + threadIdx.x;
    if (i < n) {
        float inv = g[i] / sqrtf(v[i] + 1e-5f);
        s[i] = inv;
        o[i] = b[i] - m[i] * inv;
    }
}

// =================== bf16 2-split helpers ==================================
__device__ __forceinline__ unsigned pack2(float x, float y) {
    __nv_bfloat162 t = __floats2bfloat162_rn(x, y);
    return reinterpret_cast<unsigned&>(t);
}
__device__ __forceinline__ void split_pair(float x, float y, unsigned& h, unsigned& l) {
    float hx = __bfloat162float(__float2bfloat16_rn(x));
    float hy = __bfloat162float(__float2bfloat16_rn(y));
    h = pack2(hx, hy);
    l = pack2(x - hx, y - hy);
}

__device__ __forceinline__ void ldsm4(uint4& r, unsigned addr) {
    asm volatile("ldmatrix.sync.aligned.m8n8.x4.shared.b16 {%0,%1,%2,%3}, [%4];"
                 : "=r"(r.x), "=r"(r.y), "=r"(r.z), "=r"(r.w) : "r"(addr));
}
__device__ __forceinline__ void cpasync16(unsigned dst, const void* src) {
    asm volatile("cp.async.cg.shared.global [%0], [%1], 16;" :: "r"(dst), "l"(src));
}

#define MMA4(C, A, B0, B1)                                                    \
    asm volatile("mma.sync.aligned.m16n8k16.row.col.f32.bf16.bf16.f32 "       \
                 "{%0,%1,%2,%3}, {%4,%5,%6,%7}, {%8,%9}, {%0,%1,%2,%3};"      \
                 : "+f"(C[0]), "+f"(C[1]), "+f"(C[2]), "+f"(C[3])             \
                 : "r"(A.x), "r"(A.y), "r"(A.z), "r"(A.w), "r"(B0), "r"(B1))

#define SQ 36

// ============ tensor-core split GEMM: C[M,N] = A[M,K] @ W[N,K]^T ===========
#define GEMM_SMEM (384 * SQ * 4)
__global__ void __launch_bounds__(256) gemm_mma(
    const float* __restrict__ A, const float* __restrict__ W,
    int M, int N, int K,
    float* __restrict__ Cf,
    unsigned* __restrict__ Chi, unsigned* __restrict__ Clo,
    const float* __restrict__ scale, const float* __restrict__ bias,
    float* __restrict__ C2, int c2cols)
{
    extern __shared__ unsigned gsm[];
    unsigned* AhS = gsm;
    unsigned* AlS = gsm + 128 * SQ;
    unsigned* WhS = gsm + 256 * SQ;
    unsigned* WlS = gsm + 320 * SQ;

    const int tid = threadIdx.x, lane = tid & 31, warp = tid >> 5;
    const int m0 = blockIdx.y * 128, n0 = blockIdx.x * 64;

    const unsigned sb = (unsigned)__cvta_generic_to_shared(gsm);
    const unsigned laneoff =
        (((lane & 7) + ((lane >> 3) & 1) * 8) * SQ + (lane >> 4) * 4) * 4;
    const unsigned aA = sb + (warp * 16 * SQ) * 4 + laneoff;
    const unsigned aAl = aA + 128 * SQ * 4;
    const unsigned aW = sb + (256 * SQ) * 4 + laneoff;
    const unsigned aWl = aW + 64 * SQ * 4;

    float S[8][4] = {};

    for (int k0 = 0; k0 < K; k0 += 64) {
        __syncthreads();
        {
            int row = tid >> 1, half = tid & 1;
            const float* src = A + (size_t)(m0 + row) * K + k0 + half * 32;
            unsigned* dh = AhS + row * SQ + half * 16;
            unsigned* dl = AlS + row * SQ + half * 16;
#pragma unroll
            for (int i = 0; i < 8; i++) {
                float4 v = *(const float4*)(src + i * 4);
                split_pair(v.x, v.y, dh[i * 2], dl[i * 2]);
                split_pair(v.z, v.w, dh[i * 2 + 1], dl[i * 2 + 1]);
            }
        }
        {
            int row = tid >> 2, q = tid & 3;
            const float* src = W + (size_t)(n0 + row) * K + k0 + q * 16;
            unsigned* dh = WhS + row * SQ + q * 8;
            unsigned* dl = WlS + row * SQ + q * 8;
#pragma unroll
            for (int i = 0; i < 4; i++) {
                float4 v = *(const float4*)(src + i * 4);
                split_pair(v.x, v.y, dh[i * 2], dl[i * 2]);
                split_pair(v.z, v.w, dh[i * 2 + 1], dl[i * 2 + 1]);
            }
        }
        __syncthreads();

#pragma unroll
        for (int kk = 0; kk < 4; kk++) {
            uint4 Ah, Al;
            ldsm4(Ah, aA + kk * 32);
            ldsm4(Al, aAl + kk * 32);
#pragma unroll
            for (int jp = 0; jp < 4; jp++) {
                uint4 Bh, Bl;
                ldsm4(Bh, aW + (jp * 16 * SQ) * 4 + kk * 32);
                ldsm4(Bl, aWl + (jp * 16 * SQ) * 4 + kk * 32);
                MMA4(S[2 * jp],     Ah, Bh.x, Bh.z);
                MMA4(S[2 * jp],     Ah, Bl.x, Bl.z);
                MMA4(S[2 * jp],     Al, Bh.x, Bh.z);
                MMA4(S[2 * jp + 1], Ah, Bh.y, Bh.w);
                MMA4(S[2 * jp + 1], Ah, Bl.y, Bl.w);
                MMA4(S[2 * jp + 1], Al, Bh.y, Bh.w);
            }
        }
    }

    const int fr = lane >> 2, fc = lane & 3;
    const int r0 = m0 + warp * 16 + fr;
    const int r1 = r0 + 8;
#pragma unroll
    for (int j = 0; j < 8; j++) {
        int col = n0 + j * 8 + fc * 2;
        float v0 = S[j][0], v1 = S[j][1], v2 = S[j][2], v3 = S[j][3];
        if (scale) {
            float s0 = scale[col], s1 = scale[col + 1];
            float b0 = bias[col],  b1 = bias[col + 1];
            v0 = v0 * s0 + b0; v1 = v1 * s1 + b1;
            v2 = v2 * s0 + b0; v3 = v3 * s1 + b1;
        }
        if (Cf) {
            *(float2*)(Cf + (size_t)r0 * N + col) = make_float2(v0, v1);
            *(float2*)(Cf + (size_t)r1 * N + col) = make_float2(v2, v3);
        }
        if (Chi) {
            unsigned h0, l0, h1, l1;
            split_pair(v0, v1, h0, l0);
            split_pair(v2, v3, h1, l1);
            int ci = col >> 1, nw = N >> 1;
            Chi[(size_t)r0 * nw + ci] = h0; Clo[(size_t)r0 * nw + ci] = l0;
            Chi[(size_t)r1 * nw + ci] = h1; Clo[(size_t)r1 * nw + ci] = l1;
        }
        if (C2 && col < c2cols) {
            *(float2*)(C2 + (size_t)r0 * c2cols + col) = make_float2(v0, v1);
            *(float2*)(C2 + (size_t)r1 * c2cols + col) = make_float2(v2, v3);
        }
    }
}

// ============ fused depthwise 3x3 + pointwise 1x1 + BN2 ====================
// One block = 64 tokens (within one batch since T%64==0). dw result kept in
// smem (k-major for the SIMT gemm), then 64x64x64 gemm vs pw, then BN affine.
__global__ void __launch_bounds__(256) dwpw_kernel(
    const float* __restrict__ ident, const float* __restrict__ Rprev,
    const float* __restrict__ dw, const float* __restrict__ pw,
    const float* __restrict__ bs, const float* __restrict__ bb,
    float* __restrict__ Rout, int s)
{
    __shared__ float Ds[64 * 68];   // [k=c][tok]
    __shared__ float Ws[64 * 68];   // [k=c][out]
    __shared__ float wsm[C4 * 9];
    const int tid = threadIdx.x;

    // stage pw transposed: Ws[c][o] = pw[o][c]
    {
        int o = tid >> 2, c0 = (tid & 3) * 16;
#pragma unroll
        for (int i = 0; i < 16; i++)
            Ws[(c0 + i) * 68 + o] = pw[o * 64 + c0 + i];
    }
    for (int i = tid; i < C4 * 9; i += 256) wsm[i] = dw[i];
    __syncthreads();

    const int t0 = blockIdx.x * 64;
#pragma unroll
    for (int r = 0; r < 16; r++) {
        int idx = r * 256 + tid;          // [tok 64][c 64]
        int c = idx & 63, lt = idx >> 6;
        int g = t0 + lt;
        int b = g / T_TOK, t = g - b * T_TOK;
        int hh = t / WW, ww = t % WW;
        const float* ib = ident + (size_t)b * T_TOK * CIN + s * C4 + c;
        const float* rb = Rprev ? (Rprev + (size_t)b * T_TOK * C4 + c) : nullptr;
        float acc = 0.f;
#pragma unroll
        for (int kh = 0; kh < 3; kh++) {
            int h2 = hh + kh - 1;
            if ((unsigned)h2 >= HH) continue;
#pragma unroll
            for (int kw = 0; kw < 3; kw++) {
                int w2 = ww + kw - 1;
                if ((unsigned)w2 >= WW) continue;
                int tt = h2 * WW + w2;
                float v = ib[(size_t)tt * CIN];
                if (rb) v += rb[(size_t)tt * C4];
                acc += v * wsm[c * 9 + kh * 3 + kw];
            }
        }
        Ds[c * 68 + lt] = acc;
    }
    __syncthreads();

    // 64x64x64 gemm: rows = tokens, cols = out channel
    const int tx = tid & 15, ty = tid >> 4;
    float acc[4][4] = {};
#pragma unroll 16
    for (int kk = 0; kk < 64; kk++) {
        float4 a = *(const float4*)(Ds + kk * 68 + ty * 4);
        float4 w = *(const float4*)(Ws + kk * 68 + tx * 4);
        float af[4] = {a.x, a.y, a.z, a.w};
        float wf[4] = {w.x, w.y, w.z, w.w};
#pragma unroll
        for (int i = 0; i < 4; i++)
#pragma unroll
            for (int j = 0; j < 4; j++)
                acc[i][j] += af[i] * wf[j];
    }
#pragma unroll
    for (int i = 0; i < 4; i++) {
        int g = t0 + ty * 4 + i;
#pragma unroll
        for (int j = 0; j < 4; j++) {
            int col = tx * 4 + j;
            Rout[(size_t)g * C4 + col] = acc[i][j] * bs[col] + bb[col];
        }
    }
}

// split + transpose V: per (sbh, 64-token tile): V[t][d] -> VT[sbh][d][t-pair]
__global__ void __launch_bounds__(256) split_vt_kernel(
    const float* __restrict__ V, unsigned* __restrict__ VTh, unsigned* __restrict__ VTl)
{
    __shared__ float sm[64 * 68];
    const int tid = threadIdx.x;
    const int y = blockIdx.y;
    const int s = y >> 3, b = (y >> 2) & 1, h = y & 3;
    const int tt = blockIdx.x * 64;
    const size_t base = ((size_t)(s * NB + b) * T_TOK + tt) * CIN + h * 64;
    {
        int row = tid >> 2, c0 = (tid & 3) * 16;
        const float4* src = (const float4*)(V + base + (size_t)row * CIN + c0);
        float4* dst = (float4*)(sm + row * 68 + c0);
#pragma unroll
        for (int i = 0; i < 4; i++) dst[i] = src[i];
    }
    __syncthreads();
    int tp = tid & 31, d0 = (tid >> 5) * 8;
#pragma unroll
    for (int i = 0; i < 8; i++) {
        int d = d0 + i;
        float v0 = sm[(2 * tp) * 68 + d];
        float v1 = sm[(2 * tp + 1) * 68 + d];
        unsigned hh2, ll2;
        split_pair(v0, v1, hh2, ll2);
        size_t o = ((size_t)y * 64 + d) * (T_TOK / 2) + blockIdx.x * 32 + tp;
        VTh[o] = hh2;
        VTl[o] = ll2;
    }
}

// ================= tensor-core flash attention =============================
// 8 warps, Q-tile 128, K-tile 64; cp.async double-buffered K/V; fixed-max
// softmax; software-pipelined ldsm (next fragment prefetched before MMAs).
#define AT_SMEM (27648 * 4)    // 110592 B
__global__ void __launch_bounds__(256, 2) attn_mma4(
    const unsigned* __restrict__ Qhg, const unsigned* __restrict__ Qlg,
    const unsigned* __restrict__ Khg, const unsigned* __restrict__ Klg,
    const unsigned* __restrict__ Vhg, const unsigned* __restrict__ Vlg,
    float* __restrict__ O)
{
    extern __shared__ unsigned smu[];
    unsigned* QhS = smu;
    unsigned* QlS = smu + 128 * SQ;

    const int tid = threadIdx.x, lane = tid & 31, warp = tid >> 5;
    const int y = blockIdx.y;
    const int s = y >> 3, b = (y >> 2) & 1, h = y & 3;
    const int t0 = blockIdx.x * 128;
    const size_t row0 = (size_t)(s * NB + b) * T_TOK;

    const unsigned sb = (unsigned)__cvta_generic_to_shared(smu);
    const unsigned laneoff =
        (((lane & 7) + ((lane >> 3) & 1) * 8) * SQ + (lane >> 4) * 4) * 4;

    // ---- stage Q (once) ----
    {
        int row = tid >> 1, off = (tid & 1) * 16;
        const uint4* sH = (const uint4*)(Qhg + (row0 + t0 + row) * 128 + h * 32 + off);
        const uint4* sL = (const uint4*)(Qlg + (row0 + t0 + row) * 128 + h * 32 + off);
        uint4* dH = (uint4*)(QhS + row * SQ + off);
        uint4* dL = (uint4*)(QlS + row * SQ + off);
#pragma unroll
        for (int i = 0; i < 4; i++) { dH[i] = sH[i]; dL[i] = sL[i]; }
    }

    const int fr = lane >> 2, fc = lane & 3;
    const int qr = warp * 16 + fr;

    const unsigned aQh = sb + (warp * 16 * SQ) * 4 + laneoff;
    const unsigned aQl = aQh + 128 * SQ * 4;

    const int srow = tid >> 2, soff = (tid & 3) * 8;
    auto issue_stage = [&](int st, int kb) {
        size_t kg = (row0 + (size_t)kb * 64 + srow) * 128 + h * 32 + soff;
        size_t vg = ((size_t)y * 64 + srow) * (T_TOK / 2) + (size_t)kb * 32 + soff;
        unsigned base = sb + (9216 + st * 9216 + srow * SQ + soff) * 4;
        cpasync16(base,                 Khg + kg);
        cpasync16(base + 16,            Khg + kg + 4);
        cpasync16(base + 2304 * 4,      Klg + kg);
        cpasync16(base + 2304 * 4 + 16, Klg + kg + 4);
        cpasync16(base + 4608 * 4,      Vhg + vg);
        cpasync16(base + 4608 * 4 + 16, Vhg + vg + 4);
        cpasync16(base + 6912 * 4,      Vlg + vg);
        cpasync16(base + 6912 * 4 + 16, Vlg + vg + 4);
    };

    float Ov[8][4] = {};
    float l0s = 0.f, l1s = 0.f;

    issue_stage(0, 0);
    asm volatile("cp.async.commit_group;");

    for (int kb = 0; kb < T_TOK / 64; kb++) {
        const int cur = kb & 1;
        if (kb + 1 < T_TOK / 64) {
            issue_stage(cur ^ 1, kb + 1);
            asm volatile("cp.async.commit_group;");
            asm volatile("cp.async.wait_group 1;");
        } else {
            asm volatile("cp.async.wait_group 0;");
        }
        __syncthreads();

        const unsigned bstg = sb + (9216 + cur * 9216) * 4 + laneoff;
        const unsigned aKh = bstg;
        const unsigned aKl = bstg + 2304 * 4;
        const unsigned aVh = bstg + 4608 * 4;
        const unsigned aVl = bstg + 6912 * 4;

        // ---- S = Q K^T : pipelined fragment loads ----
        float S[8][4];
#pragma unroll
        for (int j = 0; j < 8; j++)
            S[j][0] = S[j][1] = S[j][2] = S[j][3] = 0.f;

        {
            uint4 Ah, Al, nAh, nAl, Bh, Bl, nBh, nBl;
            ldsm4(Ah, aQh);
            ldsm4(Al, aQl);
            ldsm4(Bh, aKh);
            ldsm4(Bl, aKl);
#pragma unroll
            for (int kk = 0; kk < 4; kk++) {
#pragma unroll
                for (int jp = 0; jp < 4; jp++) {
                    const int ni = kk * 4 + jp + 1;
                    if (ni < 16) {
                        const int nkk = ni >> 2, njp = ni & 3;
                        ldsm4(nBh, aKh + (njp * 16 * SQ) * 4 + nkk * 32);
                        ldsm4(nBl, aKl + (njp * 16 * SQ) * 4 + nkk * 32);
                    }
                    if (jp == 3 && kk < 3) {
                        ldsm4(nAh, aQh + (kk + 1) * 32);
                        ldsm4(nAl, aQl + (kk + 1) * 32);
                    }
                    MMA4(S[2 * jp],     Ah, Bh.x, Bh.z);
                    MMA4(S[2 * jp],     Ah, Bl.x, Bl.z);
                    MMA4(S[2 * jp],     Al, Bh.x, Bh.z);
                    MMA4(S[2 * jp + 1], Ah, Bh.y, Bh.w);
                    MMA4(S[2 * jp + 1], Ah, Bl.y, Bl.w);
                    MMA4(S[2 * jp + 1], Al, Bh.y, Bh.w);
                    Bh = nBh; Bl = nBl;
                    if (jp == 3) { Ah = nAh; Al = nAl; }
                }
            }
        }

        // ---- softmax (fixed max = 0) + PV, pipelined ----
        {
            uint4 Ph, Pl, Bh, Bl, nBh, nBl;
            ldsm4(Bh, aVh);
            ldsm4(Bl, aVl);
#pragma unroll
            for (int kk = 0; kk < 4; kk++) {
                const int j0 = 2 * kk, j1 = 2 * kk + 1;
                float p00 = __expf(S[j0][0]), p01 = __expf(S[j0][1]);
                float p02 = __expf(S[j0][2]), p03 = __expf(S[j0][3]);
                float p10 = __expf(S[j1][0]), p11 = __expf(S[j1][1]);
                float p12 = __expf(S[j1][2]), p13 = __expf(S[j1][3]);
                l0s += (p00 + p01) + (p10 + p11);
                l1s += (p02 + p03) + (p12 + p13);
                split_pair(p00, p01, Ph.x, Pl.x);
                split_pair(p02, p03, Ph.y, Pl.y);
                split_pair(p10, p11, Ph.z, Pl.z);
                split_pair(p12, p13, Ph.w, Pl.w);
#pragma unroll
                for (int jp = 0; jp < 4; jp++) {
                    const int ni = kk * 4 + jp + 1;
                    if (ni < 16) {
                        const int nkk = ni >> 2, njp = ni & 3;
                        ldsm4(nBh, aVh + (njp * 16 * SQ) * 4 + nkk * 32);
                        ldsm4(nBl, aVl + (njp * 16 * SQ) * 4 + nkk * 32);
                    }
                    MMA4(Ov[2 * jp],     Ph, Bh.x, Bh.z);
                    MMA4(Ov[2 * jp],     Ph, Bl.x, Bl.z);
                    MMA4(Ov[2 * jp],     Pl, Bh.x, Bh.z);
                    MMA4(Ov[2 * jp + 1], Ph, Bh.y, Bh.w);
                    MMA4(Ov[2 * jp + 1], Ph, Bl.y, Bl.w);
                    MMA4(Ov[2 * jp + 1], Pl, Bh.y, Bh.w);
                    Bh = nBh; Bl = nBl;
                }
            }
        }
        __syncthreads();
    }

    // ---- epilogue: reduce l over the quad, normalize, store ----
    l0s += __shfl_xor_sync(0xffffffffu, l0s, 1);
    l0s += __shfl_xor_sync(0xffffffffu, l0s, 2);
    l1s += __shfl_xor_sync(0xffffffffu, l1s, 1);
    l1s += __shfl_xor_sync(0xffffffffu, l1s, 2);
    float inv0 = 1.0f / l0s, inv1 = 1.0f / l1s;
    const size_t feat0 = (size_t)s * CIN + h * DH;
    const size_t r0g = (size_t)b * T_TOK + t0 + qr;
    const size_t r1g = r0g + 8;
#pragma unroll
    for (int j = 0; j < 8; j++) {
        size_t col = feat0 + j * 8 + fc * 2;
        *(float2*)(O + r0g * (4 * CIN) + col) = make_float2(Ov[j][0] * inv0, Ov[j][1] * inv0);
        *(float2*)(O + r1g * (4 * CIN) + col) = make_float2(Ov[j][2] * inv1, Ov[j][3] * inv1);
    }
}

// ---------------------------------------------------------------------------
extern "C" void kernel_launch(void* const* d_in, const int* in_sizes, int n_in,
                              void* d_out, int out_size)
{
    const float* x    = (const float*)d_in[0];
    const float* w1   = (const float*)d_in[1];
    const float* bn1g = (const float*)d_in[2];
    const float* bn1b = (const float*)d_in[3];
    const float* bn1m = (const float*)d_in[4];
    const float* bn1v = (const float*)d_in[5];
    const float* dww  = (const float*)d_in[6];
    const float* pww  = (const float*)d_in[7];
    const float* bn2g = (const float*)d_in[8];
    const float* bn2b = (const float*)d_in[9];
    const float* bn2m = (const float*)d_in[10];
    const float* bn2v = (const float*)d_in[11];
    const float* Wq   = (const float*)d_in[12];
    const float* Wk   = (const float*)d_in[13];
    const float* Wv   = (const float*)d_in[14];
    const float* Wout = (const float*)d_in[15];
    float* out = (float*)d_out;

    void* p;
    cudaGetSymbolAddress(&p, g_identity); float* ident = (float*)p;
    cudaGetSymbolAddress(&p, g_R);        float* Rp    = (float*)p;
    cudaGetSymbolAddress(&p, g_V);        float* Vp    = (float*)p;
    cudaGetSymbolAddress(&p, g_O);        float* Op    = (float*)p;
    cudaGetSymbolAddress(&p, g_bn1s);     float* b1s   = (float*)p;
    cudaGetSymbolAddress(&p, g_bn1bb);    float* b1b   = (float*)p;
    cudaGetSymbolAddress(&p, g_bn2s);     float* b2s   = (float*)p;
    cudaGetSymbolAddress(&p, g_bn2bb);    float* b2b   = (float*)p;
    cudaGetSymbolAddress(&p, g_Qh);  unsigned* Qh = (unsigned*)p;
    cudaGetSymbolAddress(&p, g_Ql);  unsigned* Ql = (unsigned*)p;
    cudaGetSymbolAddress(&p, g_Kh);  unsigned* Kh = (unsigned*)p;
    cudaGetSymbolAddress(&p, g_Kl);  unsigned* Kl = (unsigned*)p;
    cudaGetSymbolAddress(&p, g_VTh); unsigned* VTh = (unsigned*)p;
    cudaGetSymbolAddress(&p, g_VTl); unsigned* VTl = (unsigned*)p;

    cudaFuncSetAttribute(gemm_mma, cudaFuncAttributeMaxDynamicSharedMemorySize, GEMM_SMEM);
    cudaFuncSetAttribute(attn_mma4, cudaFuncAttributeMaxDynamicSharedMemorySize, AT_SMEM);

    bn_prep_kernel<<<1, 256>>>(bn1g, bn1b, bn1m, bn1v, b1s, b1b, CIN);
    bn_prep_kernel<<<1, 64>>>(bn2g, bn2b, bn2m, bn2v, b2s, b2b, C4);

    // conv_in + BN1 -> identity ; channels [0,64) also into R[0]
    gemm_mma<<<dim3(4, 36), 256, GEMM_SMEM>>>(
        x, w1, NB * T_TOK, CIN, CIN, ident, nullptr, nullptr, b1s, b1b, Rp, C4);

    // Res2Net scales 1..3 (fused dw+pw+BN, sequential dependency)
    for (int s = 1; s <= 3; s++) {
        const float* prev = (s == 1) ? nullptr : (Rp + (size_t)(s - 1) * NB * T_TOK * C4);
        dwpw_kernel<<<(NB * T_TOK) / 64, 256>>>(
            ident, prev, dww, pww, b2s, b2b, Rp + (size_t)s * NB * T_TOK * C4, s);
    }

    // Q/K projections -> pre-split hi/lo directly ; V -> f32 then transpose-split
    gemm_mma<<<dim3(4, 144), 256, GEMM_SMEM>>>(
        Rp, Wq, NS * NB * T_TOK, CIN, C4, nullptr, Qh, Ql, nullptr, nullptr, nullptr, 0);
    gemm_mma<<<dim3(4, 144), 256, GEMM_SMEM>>>(
        Rp, Wk, NS * NB * T_TOK, CIN, C4, nullptr, Kh, Kl, nullptr, nullptr, nullptr, 0);
    gemm_mma<<<dim3(4, 144), 256, GEMM_SMEM>>>(
        Rp, Wv, NS * NB * T_TOK, CIN, C4, Vp, nullptr, nullptr, nullptr, nullptr, nullptr, 0);
    split_vt_kernel<<<dim3(T_TOK / 64, NS * NB * NH), 256>>>(Vp, VTh, VTl);

    // flash attention (cp.async double-buffered, pipelined ldsm)
    attn_mma4<<<dim3(T_TOK / 128, NS * NB * NH), 256, AT_SMEM>>>(
        Qh, Ql, Kh, Kl, VTh, VTl, Op);

    // output projection -> d_out
    gemm_mma<<<dim3(4, 36), 256, GEMM_SMEM>>>(
        Op, Wout, NB * T_TOK, CIN, 4 * CIN, out, nullptr, nullptr, nullptr, nullptr, nullptr, 0);
}

// round 8
// speedup vs baseline: 1.1122x; 1.1122x over previous
#include <cuda_runtime.h>
#include <cuda_bf16.h>

// Problem constants (fixed shapes)
#define T_TOK 2304
#define NB    2
#define CIN   256
#define C4    64
#define NS    4
#define NH    4
#define DH    64
#define HH    48
#define WW    48

// ---------------- scratch (device globals; no allocation allowed) ----------
__device__ __align__(128) float g_identity[NB * T_TOK * CIN];
__device__ __align__(128) float g_R[NS * NB * T_TOK * C4];
__device__ __align__(128) float g_O[NB * T_TOK * 4 * CIN];
#define NPAIR (NS * NB * T_TOK * (CIN / 2))
__device__ __align__(128) unsigned g_Qh[NPAIR], g_Ql[NPAIR];
__device__ __align__(128) unsigned g_Kh[NPAIR], g_Kl[NPAIR];
__device__ __align__(128) unsigned g_Vh[NPAIR], g_Vl[NPAIR];

// =================== bf16 2-split helpers ==================================
__device__ __forceinline__ unsigned pack2(float x, float y) {
    __nv_bfloat162 t = __floats2bfloat162_rn(x, y);
    return reinterpret_cast<unsigned&>(t);
}
__device__ __forceinline__ void split_pair(float x, float y, unsigned& h, unsigned& l) {
    float hx = __bfloat162float(__float2bfloat16_rn(x));
    float hy = __bfloat162float(__float2bfloat16_rn(y));
    h = pack2(hx, hy);
    l = pack2(x - hx, y - hy);
}
__device__ __forceinline__ void ldsm4(uint4& r, unsigned addr) {
    asm volatile("ldmatrix.sync.aligned.m8n8.x4.shared.b16 {%0,%1,%2,%3}, [%4];"
                 : "=r"(r.x), "=r"(r.y), "=r"(r.z), "=r"(r.w) : "r"(addr));
}
__device__ __forceinline__ void ldsm4t(uint4& r, unsigned addr) {
    asm volatile("ldmatrix.sync.aligned.m8n8.x4.trans.shared.b16 {%0,%1,%2,%3}, [%4];"
                 : "=r"(r.x), "=r"(r.y), "=r"(r.z), "=r"(r.w) : "r"(addr));
}
__device__ __forceinline__ void cpasync16(unsigned dst, const void* src) {
    asm volatile("cp.async.cg.shared.global [%0], [%1], 16;" :: "r"(dst), "l"(src));
}
__device__ __forceinline__ unsigned smem_u32(const void* p) {
    return (unsigned)__cvta_generic_to_shared(p);
}
__device__ __forceinline__ float fexp2(float x) {
    float y;
    asm("ex2.approx.f32 %0, %1;" : "=f"(y) : "f"(x));
    return y;
}

#define MMA4(C, A, B0, B1)                                                    \
    asm volatile("mma.sync.aligned.m16n8k16.row.col.f32.bf16.bf16.f32 "       \
                 "{%0,%1,%2,%3}, {%4,%5,%6,%7}, {%8,%9}, {%0,%1,%2,%3};"      \
                 : "+f"(C[0]), "+f"(C[1]), "+f"(C[2]), "+f"(C[3])             \
                 : "r"(A.x), "r"(A.y), "r"(A.z), "r"(A.w), "r"(B0), "r"(B1))

#define SQ 36

// ============ tensor-core split GEMM: C[M,N] = A[M,K] @ W[N,K]^T ===========
// BN (eval) folded inline from raw g/b/m/v when bng != nullptr.
#define GEMM_SMEM (384 * SQ * 4)
__global__ void __launch_bounds__(256) gemm_mma(
    const float* __restrict__ A, const float* __restrict__ W,
    int M, int N, int K,
    float* __restrict__ Cf,
    const float* __restrict__ bng, const float* __restrict__ bnb,
    const float* __restrict__ bnm, const float* __restrict__ bnv,
    float* __restrict__ C2, int c2cols)
{
    extern __shared__ unsigned gsm[];
    unsigned* AhS = gsm;
    unsigned* AlS = gsm + 128 * SQ;
    unsigned* WhS = gsm + 256 * SQ;
    unsigned* WlS = gsm + 320 * SQ;

    const int tid = threadIdx.x, lane = tid & 31, warp = tid >> 5;
    const int m0 = blockIdx.y * 128, n0 = blockIdx.x * 64;

    const unsigned sb = smem_u32(gsm);
    const unsigned laneoff =
        (((lane & 7) + ((lane >> 3) & 1) * 8) * SQ + (lane >> 4) * 4) * 4;
    const unsigned aA = sb + (warp * 16 * SQ) * 4 + laneoff;
    const unsigned aAl = aA + 128 * SQ * 4;
    const unsigned aW = sb + (256 * SQ) * 4 + laneoff;
    const unsigned aWl = aW + 64 * SQ * 4;

    float S[8][4] = {};

    for (int k0 = 0; k0 < K; k0 += 64) {
        __syncthreads();
        {
            int row = tid >> 1, half = tid & 1;
            const float* src = A + (size_t)(m0 + row) * K + k0 + half * 32;
            unsigned* dh = AhS + row * SQ + half * 16;
            unsigned* dl = AlS + row * SQ + half * 16;
#pragma unroll
            for (int i = 0; i < 8; i++) {
                float4 v = *(const float4*)(src + i * 4);
                split_pair(v.x, v.y, dh[i * 2], dl[i * 2]);
                split_pair(v.z, v.w, dh[i * 2 + 1], dl[i * 2 + 1]);
            }
        }
        {
            int row = tid >> 2, q = tid & 3;
            const float* src = W + (size_t)(n0 + row) * K + k0 + q * 16;
            unsigned* dh = WhS + row * SQ + q * 8;
            unsigned* dl = WlS + row * SQ + q * 8;
#pragma unroll
            for (int i = 0; i < 4; i++) {
                float4 v = *(const float4*)(src + i * 4);
                split_pair(v.x, v.y, dh[i * 2], dl[i * 2]);
                split_pair(v.z, v.w, dh[i * 2 + 1], dl[i * 2 + 1]);
            }
        }
        __syncthreads();

#pragma unroll
        for (int kk = 0; kk < 4; kk++) {
            uint4 Ah, Al;
            ldsm4(Ah, aA + kk * 32);
            ldsm4(Al, aAl + kk * 32);
#pragma unroll
            for (int jp = 0; jp < 4; jp++) {
                uint4 Bh, Bl;
                ldsm4(Bh, aW + (jp * 16 * SQ) * 4 + kk * 32);
                ldsm4(Bl, aWl + (jp * 16 * SQ) * 4 + kk * 32);
                MMA4(S[2 * jp],     Ah, Bh.x, Bh.z);
                MMA4(S[2 * jp],     Ah, Bl.x, Bl.z);
                MMA4(S[2 * jp],     Al, Bh.x, Bh.z);
                MMA4(S[2 * jp + 1], Ah, Bh.y, Bh.w);
                MMA4(S[2 * jp + 1], Ah, Bl.y, Bl.w);
                MMA4(S[2 * jp + 1], Al, Bh.y, Bh.w);
            }
        }
    }

    const int fr = lane >> 2, fc = lane & 3;
    const int r0 = m0 + warp * 16 + fr;
    const int r1 = r0 + 8;
#pragma unroll
    for (int j = 0; j < 8; j++) {
        int col = n0 + j * 8 + fc * 2;
        float v0 = S[j][0], v1 = S[j][1], v2 = S[j][2], v3 = S[j][3];
        if (bng) {
            float s0 = bng[col] * rsqrtf(bnv[col] + 1e-5f);
            float s1 = bng[col + 1] * rsqrtf(bnv[col + 1] + 1e-5f);
            float b0 = bnb[col] - bnm[col] * s0;
            float b1 = bnb[col + 1] - bnm[col + 1] * s1;
            v0 = v0 * s0 + b0; v1 = v1 * s1 + b1;
            v2 = v2 * s0 + b0; v3 = v3 * s1 + b1;
        }
        *(float2*)(Cf + (size_t)r0 * N + col) = make_float2(v0, v1);
        *(float2*)(Cf + (size_t)r1 * N + col) = make_float2(v2, v3);
        if (C2 && col < c2cols) {
            *(float2*)(C2 + (size_t)r0 * c2cols + col) = make_float2(v0, v1);
            *(float2*)(C2 + (size_t)r1 * c2cols + col) = make_float2(v2, v3);
        }
    }
}

// ============ fused QKV projection (single launch, grid.z selects) =========
// A[M=18432, K=64] @ W[256, 64]^T ; epilogue writes pre-split hi/lo u32.
// z==0 (Q) additionally scales by log2(e) so attention can use ex2 directly.
__global__ void __launch_bounds__(256) gemm_qkv(
    const float* __restrict__ A,
    const float* __restrict__ Wq, const float* __restrict__ Wk, const float* __restrict__ Wv,
    unsigned* __restrict__ Qh, unsigned* __restrict__ Ql,
    unsigned* __restrict__ Kh, unsigned* __restrict__ Kl,
    unsigned* __restrict__ Vh, unsigned* __restrict__ Vl)
{
    extern __shared__ unsigned gsm[];
    unsigned* AhS = gsm;
    unsigned* AlS = gsm + 128 * SQ;
    unsigned* WhS = gsm + 256 * SQ;
    unsigned* WlS = gsm + 320 * SQ;

    const int tid = threadIdx.x, lane = tid & 31, warp = tid >> 5;
    const int m0 = blockIdx.y * 128, n0 = blockIdx.x * 64;
    const int z = blockIdx.z;
    const float* W = (z == 0) ? Wq : (z == 1) ? Wk : Wv;
    unsigned* Chi = (z == 0) ? Qh : (z == 1) ? Kh : Vh;
    unsigned* Clo = (z == 0) ? Ql : (z == 1) ? Kl : Vl;
    const float mult = (z == 0) ? 1.4426950408889634f : 1.0f;
    const int K = C4, N = CIN;

    const unsigned sb = smem_u32(gsm);
    const unsigned laneoff =
        (((lane & 7) + ((lane >> 3) & 1) * 8) * SQ + (lane >> 4) * 4) * 4;
    const unsigned aA = sb + (warp * 16 * SQ) * 4 + laneoff;
    const unsigned aAl = aA + 128 * SQ * 4;
    const unsigned aW = sb + (256 * SQ) * 4 + laneoff;
    const unsigned aWl = aW + 64 * SQ * 4;

    float S[8][4] = {};

    // single k-slab (K = 64)
    {
        int row = tid >> 1, half = tid & 1;
        const float* src = A + (size_t)(m0 + row) * K + half * 32;
        unsigned* dh = AhS + row * SQ + half * 16;
        unsigned* dl = AlS + row * SQ + half * 16;
#pragma unroll
        for (int i = 0; i < 8; i++) {
            float4 v = *(const float4*)(src + i * 4);
            split_pair(v.x, v.y, dh[i * 2], dl[i * 2]);
            split_pair(v.z, v.w, dh[i * 2 + 1], dl[i * 2 + 1]);
        }
    }
    {
        int row = tid >> 2, q = tid & 3;
        const float* src = W + (size_t)(n0 + row) * K + q * 16;
        unsigned* dh = WhS + row * SQ + q * 8;
        unsigned* dl = WlS + row * SQ + q * 8;
#pragma unroll
        for (int i = 0; i < 4; i++) {
            float4 v = *(const float4*)(src + i * 4);
            split_pair(v.x, v.y, dh[i * 2], dl[i * 2]);
            split_pair(v.z, v.w, dh[i * 2 + 1], dl[i * 2 + 1]);
        }
    }
    __syncthreads();

#pragma unroll
    for (int kk = 0; kk < 4; kk++) {
        uint4 Ah, Al;
        ldsm4(Ah, aA + kk * 32);
        ldsm4(Al, aAl + kk * 32);
#pragma unroll
        for (int jp = 0; jp < 4; jp++) {
            uint4 Bh, Bl;
            ldsm4(Bh, aW + (jp * 16 * SQ) * 4 + kk * 32);
            ldsm4(Bl, aWl + (jp * 16 * SQ) * 4 + kk * 32);
            MMA4(S[2 * jp],     Ah, Bh.x, Bh.z);
            MMA4(S[2 * jp],     Ah, Bl.x, Bl.z);
            MMA4(S[2 * jp],     Al, Bh.x, Bh.z);
            MMA4(S[2 * jp + 1], Ah, Bh.y, Bh.w);
            MMA4(S[2 * jp + 1], Ah, Bl.y, Bl.w);
            MMA4(S[2 * jp + 1], Al, Bh.y, Bh.w);
        }
    }

    const int fr = lane >> 2, fc = lane & 3;
    const int r0 = m0 + warp * 16 + fr;
    const int r1 = r0 + 8;
#pragma unroll
    for (int j = 0; j < 8; j++) {
        int col = n0 + j * 8 + fc * 2;
        float v0 = S[j][0] * mult, v1 = S[j][1] * mult;
        float v2 = S[j][2] * mult, v3 = S[j][3] * mult;
        unsigned h0, l0, h1, l1;
        split_pair(v0, v1, h0, l0);
        split_pair(v2, v3, h1, l1);
        int ci = col >> 1, nw = N >> 1;
        Chi[(size_t)r0 * nw + ci] = h0; Clo[(size_t)r0 * nw + ci] = l0;
        Chi[(size_t)r1 * nw + ci] = h1; Clo[(size_t)r1 * nw + ci] = l1;
    }
}

// ============ fused depthwise 3x3 + pointwise 1x1 + BN2 (32-token blocks) ==
__global__ void __launch_bounds__(256) dwpw32(
    const float* __restrict__ ident, const float* __restrict__ Rprev,
    const float* __restrict__ dw, const float* __restrict__ pw,
    const float* __restrict__ bn2g, const float* __restrict__ bn2b,
    const float* __restrict__ bn2m, const float* __restrict__ bn2v,
    float* __restrict__ Rout, int s)
{
    __shared__ float Ws[64 * 68];   // [k=c][out]
    __shared__ float Ds[64 * 36];   // [k=c][tok 32 pad]
    __shared__ float wsm[C4 * 9];
    const int tid = threadIdx.x;

    {
        int o = tid & 63, c0 = (tid >> 6) * 16;
#pragma unroll
        for (int i = 0; i < 16; i++)
            Ws[(c0 + i) * 68 + o] = pw[o * 64 + c0 + i];
    }
    for (int i = tid; i < C4 * 9; i += 256) wsm[i] = dw[i];
    __syncthreads();

    const int t0 = blockIdx.x * 32;
#pragma unroll
    for (int r = 0; r < 8; r++) {
        int idx = r * 256 + tid;          // [tok 32][c 64]
        int c = idx & 63, lt = idx >> 6;
        int g = t0 + lt;
        int b = g / T_TOK, t = g - b * T_TOK;
        int hh = t / WW, ww = t % WW;
        const float* ib = ident + (size_t)b * T_TOK * CIN + s * C4 + c;
        const float* rb = Rprev ? (Rprev + (size_t)b * T_TOK * C4 + c) : nullptr;
        float acc = 0.f;
#pragma unroll
        for (int kh = 0; kh < 3; kh++) {
            int h2 = hh + kh - 1;
            if ((unsigned)h2 >= HH) continue;
#pragma unroll
            for (int kw = 0; kw < 3; kw++) {
                int w2 = ww + kw - 1;
                if ((unsigned)w2 >= WW) continue;
                int tt = h2 * WW + w2;
                float v = ib[(size_t)tt * CIN];
                if (rb) v += rb[(size_t)tt * C4];
                acc += v * wsm[c * 9 + kh * 3 + kw];
            }
        }
        Ds[c * 36 + lt] = acc;
    }
    __syncthreads();

    // 32x64x64 gemm: ty = token pair, tx = 4 out-cols
    const int tx = tid & 15, ty = tid >> 4;
    float acc[2][4] = {};
#pragma unroll 16
    for (int kk = 0; kk < 64; kk++) {
        float2 a = *(const float2*)(Ds + kk * 36 + ty * 2);
        float4 w = *(const float4*)(Ws + kk * 68 + tx * 4);
        acc[0][0] += a.x * w.x; acc[0][1] += a.x * w.y;
        acc[0][2] += a.x * w.z; acc[0][3] += a.x * w.w;
        acc[1][0] += a.y * w.x; acc[1][1] += a.y * w.y;
        acc[1][2] += a.y * w.z; acc[1][3] += a.y * w.w;
    }
#pragma unroll
    for (int j = 0; j < 4; j++) {
        int col = tx * 4 + j;
        float sc = bn2g[col] * rsqrtf(bn2v[col] + 1e-5f);
        float bi = bn2b[col] - bn2m[col] * sc;
        Rout[(size_t)(t0 + ty * 2 + 0) * C4 + col] = acc[0][j] * sc + bi;
        Rout[(size_t)(t0 + ty * 2 + 1) * C4 + col] = acc[1][j] * sc + bi;
    }
}

// ================= tensor-core flash attention =============================
// 8 warps, Q-tile 128, K-tile 64; cp.async double-buffered K/V; fixed-max
// softmax with Q pre-scaled by log2e (ex2). V via ldmatrix.trans (no VT array).
#define AT_SMEM (27648 * 4)    // 110592 B -> 2 CTAs/SM
__global__ void __launch_bounds__(256, 2) attn5(
    const unsigned* __restrict__ Qhg, const unsigned* __restrict__ Qlg,
    const unsigned* __restrict__ Khg, const unsigned* __restrict__ Klg,
    const unsigned* __restrict__ Vhg, const unsigned* __restrict__ Vlg,
    float* __restrict__ O)
{
    extern __shared__ unsigned smu[];
    unsigned* QhS = smu;
    unsigned* QlS = smu + 128 * SQ;

    const int tid = threadIdx.x, lane = tid & 31, warp = tid >> 5;
    const int y = blockIdx.y;
    const int s = y >> 3, b = (y >> 2) & 1, h = y & 3;
    const int t0 = blockIdx.x * 128;
    const size_t row0 = (size_t)(s * NB + b) * T_TOK;

    const unsigned sb = smem_u32(smu);
    const unsigned laneoff =
        (((lane & 7) + ((lane >> 3) & 1) * 8) * SQ + (lane >> 4) * 4) * 4;

    // ---- stage Q (once) ----
    {
        int row = tid >> 1, off = (tid & 1) * 16;
        const uint4* sH = (const uint4*)(Qhg + (row0 + t0 + row) * 128 + h * 32 + off);
        const uint4* sL = (const uint4*)(Qlg + (row0 + t0 + row) * 128 + h * 32 + off);
        uint4* dH = (uint4*)(QhS + row * SQ + off);
        uint4* dL = (uint4*)(QlS + row * SQ + off);
#pragma unroll
        for (int i = 0; i < 4; i++) { dH[i] = sH[i]; dL[i] = sL[i]; }
    }

    const int fr = lane >> 2, fc = lane & 3;
    const int qr = warp * 16 + fr;

    const unsigned aQh = sb + (warp * 16 * SQ) * 4 + laneoff;
    const unsigned aQl = aQh + 128 * SQ * 4;

    const int srow = tid >> 2, soff = (tid & 3) * 8;
    auto issue_stage = [&](int st, int kb) {
        size_t kg = (row0 + (size_t)kb * 64 + srow) * 128 + h * 32 + soff;
        unsigned base = sb + (9216 + st * 9216 + srow * SQ + soff) * 4;
        cpasync16(base,                 Khg + kg);
        cpasync16(base + 16,            Khg + kg + 4);
        cpasync16(base + 2304 * 4,      Klg + kg);
        cpasync16(base + 2304 * 4 + 16, Klg + kg + 4);
        cpasync16(base + 4608 * 4,      Vhg + kg);
        cpasync16(base + 4608 * 4 + 16, Vhg + kg + 4);
        cpasync16(base + 6912 * 4,      Vlg + kg);
        cpasync16(base + 6912 * 4 + 16, Vlg + kg + 4);
    };

    float Ov[8][4] = {};
    float l0s = 0.f, l1s = 0.f;

    issue_stage(0, 0);
    asm volatile("cp.async.commit_group;");

    for (int kb = 0; kb < T_TOK / 64; kb++) {
        const int cur = kb & 1;
        if (kb + 1 < T_TOK / 64) {
            issue_stage(cur ^ 1, kb + 1);
            asm volatile("cp.async.commit_group;");
            asm volatile("cp.async.wait_group 1;");
        } else {
            asm volatile("cp.async.wait_group 0;");
        }
        __syncthreads();

        const unsigned bstg = sb + (9216 + cur * 9216) * 4 + laneoff;
        const unsigned aKh = bstg;
        const unsigned aKl = bstg + 2304 * 4;
        const unsigned aVh = bstg + 4608 * 4;
        const unsigned aVl = bstg + 6912 * 4;

        // ---- S = Q K^T : 16x64 per warp ----
        float S[8][4];
#pragma unroll
        for (int j = 0; j < 8; j++)
            S[j][0] = S[j][1] = S[j][2] = S[j][3] = 0.f;

#pragma unroll
        for (int kk = 0; kk < 4; kk++) {
            uint4 Ah, Al;
            ldsm4(Ah, aQh + kk * 32);
            ldsm4(Al, aQl + kk * 32);
#pragma unroll
            for (int jp = 0; jp < 4; jp++) {
                uint4 Bh, Bl;
                ldsm4(Bh, aKh + (jp * 16 * SQ) * 4 + kk * 32);
                ldsm4(Bl, aKl + (jp * 16 * SQ) * 4 + kk * 32);
                MMA4(S[2 * jp],     Ah, Bh.x, Bh.z);
                MMA4(S[2 * jp],     Ah, Bl.x, Bl.z);
                MMA4(S[2 * jp],     Al, Bh.x, Bh.z);
                MMA4(S[2 * jp + 1], Ah, Bh.y, Bh.w);
                MMA4(S[2 * jp + 1], Ah, Bl.y, Bl.w);
                MMA4(S[2 * jp + 1], Al, Bh.y, Bh.w);
            }
        }

        // ---- softmax (fixed max 0; Q pre-scaled by log2e -> ex2) + PV ----
#pragma unroll
        for (int kk = 0; kk < 4; kk++) {
            const int j0 = 2 * kk, j1 = 2 * kk + 1;
            float p00 = fexp2(S[j0][0]), p01 = fexp2(S[j0][1]);
            float p02 = fexp2(S[j0][2]), p03 = fexp2(S[j0][3]);
            float p10 = fexp2(S[j1][0]), p11 = fexp2(S[j1][1]);
            float p12 = fexp2(S[j1][2]), p13 = fexp2(S[j1][3]);
            l0s += (p00 + p01) + (p10 + p11);
            l1s += (p02 + p03) + (p12 + p13);
            uint4 Ph, Pl;
            split_pair(p00, p01, Ph.x, Pl.x);
            split_pair(p02, p03, Ph.y, Pl.y);
            split_pair(p10, p11, Ph.z, Pl.z);
            split_pair(p12, p13, Ph.w, Pl.w);
#pragma unroll
            for (int jp = 0; jp < 4; jp++) {
                uint4 Bh, Bl;
                ldsm4t(Bh, aVh + (kk * 16 * SQ) * 4 + jp * 32);
                ldsm4t(Bl, aVl + (kk * 16 * SQ) * 4 + jp * 32);
                MMA4(Ov[2 * jp],     Ph, Bh.x, Bh.y);
                MMA4(Ov[2 * jp],     Ph, Bl.x, Bl.y);
                MMA4(Ov[2 * jp],     Pl, Bh.x, Bh.y);
                MMA4(Ov[2 * jp + 1], Ph, Bh.z, Bh.w);
                MMA4(Ov[2 * jp + 1], Ph, Bl.z, Bl.w);
                MMA4(Ov[2 * jp + 1], Pl, Bh.z, Bh.w);
            }
        }
        __syncthreads();
    }

    // ---- epilogue: reduce l over the quad, normalize, store ----
    l0s += __shfl_xor_sync(0xffffffffu, l0s, 1);
    l0s += __shfl_xor_sync(0xffffffffu, l0s, 2);
    l1s += __shfl_xor_sync(0xffffffffu, l1s, 1);
    l1s += __shfl_xor_sync(0xffffffffu, l1s, 2);
    float inv0 = 1.0f / l0s, inv1 = 1.0f / l1s;
    const size_t feat0 = (size_t)s * CIN + h * DH;
    const size_t r0g = (size_t)b * T_TOK + t0 + qr;
    const size_t r1g = r0g + 8;
#pragma unroll
    for (int j = 0; j < 8; j++) {
        size_t col = feat0 + j * 8 + fc * 2;
        *(float2*)(O + r0g * (4 * CIN) + col) = make_float2(Ov[j][0] * inv0, Ov[j][1] * inv0);
        *(float2*)(O + r1g * (4 * CIN) + col) = make_float2(Ov[j][2] * inv1, Ov[j][3] * inv1);
    }
}

// ---------------------------------------------------------------------------
extern "C" void kernel_launch(void* const* d_in, const int* in_sizes, int n_in,
                              void* d_out, int out_size)
{
    const float* x    = (const float*)d_in[0];
    const float* w1   = (const float*)d_in[1];
    const float* bn1g = (const float*)d_in[2];
    const float* bn1b = (const float*)d_in[3];
    const float* bn1m = (const float*)d_in[4];
    const float* bn1v = (const float*)d_in[5];
    const float* dww  = (const float*)d_in[6];
    const float* pww  = (const float*)d_in[7];
    const float* bn2g = (const float*)d_in[8];
    const float* bn2b = (const float*)d_in[9];
    const float* bn2m = (const float*)d_in[10];
    const float* bn2v = (const float*)d_in[11];
    const float* Wq   = (const float*)d_in[12];
    const float* Wk   = (const float*)d_in[13];
    const float* Wv   = (const float*)d_in[14];
    const float* Wout = (const float*)d_in[15];
    float* out = (float*)d_out;

    void* p;
    cudaGetSymbolAddress(&p, g_identity); float* ident = (float*)p;
    cudaGetSymbolAddress(&p, g_R);        float* Rp    = (float*)p;
    cudaGetSymbolAddress(&p, g_O);        float* Op    = (float*)p;
    cudaGetSymbolAddress(&p, g_Qh);  unsigned* Qh = (unsigned*)p;
    cudaGetSymbolAddress(&p, g_Ql);  unsigned* Ql = (unsigned*)p;
    cudaGetSymbolAddress(&p, g_Kh);  unsigned* Kh = (unsigned*)p;
    cudaGetSymbolAddress(&p, g_Kl);  unsigned* Kl = (unsigned*)p;
    cudaGetSymbolAddress(&p, g_Vh);  unsigned* Vh = (unsigned*)p;
    cudaGetSymbolAddress(&p, g_Vl);  unsigned* Vl = (unsigned*)p;

    cudaFuncSetAttribute(gemm_mma, cudaFuncAttributeMaxDynamicSharedMemorySize, GEMM_SMEM);
    cudaFuncSetAttribute(gemm_qkv, cudaFuncAttributeMaxDynamicSharedMemorySize, GEMM_SMEM);
    cudaFuncSetAttribute(attn5, cudaFuncAttributeMaxDynamicSharedMemorySize, AT_SMEM);

    // [0] conv_in + BN1 (inline) -> identity ; channels [0,64) also into R[0]
    gemm_mma<<<dim3(4, 36), 256, GEMM_SMEM>>>(
        x, w1, NB * T_TOK, CIN, CIN, ident, bn1g, bn1b, bn1m, bn1v, Rp, C4);

    // [1..3] Res2Net scales (fused dw+pw+BN2, 32-token blocks)
    for (int s = 1; s <= 3; s++) {
        const float* prev = (s == 1) ? nullptr : (Rp + (size_t)(s - 1) * NB * T_TOK * C4);
        dwpw32<<<(NB * T_TOK) / 32, 256>>>(
            ident, prev, dww, pww, bn2g, bn2b, bn2m, bn2v,
            Rp + (size_t)s * NB * T_TOK * C4, s);
    }

    // [4] fused Q/K/V projections -> pre-split hi/lo (Q scaled by log2e)
    gemm_qkv<<<dim3(4, 144, 3), 256, GEMM_SMEM>>>(
        Rp, Wq, Wk, Wv, Qh, Ql, Kh, Kl, Vh, Vl);

    // [5] flash attention  (profiled by ncu -s 5 -c 1)
    attn5<<<dim3(T_TOK / 128, NS * NB * NH), 256, AT_SMEM>>>(
        Qh, Ql, Kh, Kl, Vh, Vl, Op);

    // [6] output projection -> d_out
    gemm_mma<<<dim3(4, 36), 256, GEMM_SMEM>>>(
        Op, Wout, NB * T_TOK, CIN, 4 * CIN, out,
        nullptr, nullptr, nullptr, nullptr, nullptr, 0);
}

// round 10
// speedup vs baseline: 1.1556x; 1.0390x over previous
#include <cuda_runtime.h>
#include <cuda_bf16.h>

// Problem constants (fixed shapes)
#define T_TOK 2304
#define NB    2
#define CIN   256
#define C4    64
#define NS    4
#define NH    4
#define DH    64
#define HH    48
#define WW    48

// ---------------- scratch (device globals; no allocation allowed) ----------
__device__ __align__(128) float g_identity[NB * T_TOK * CIN];
__device__ __align__(128) float g_R[NS * NB * T_TOK * C4];
__device__ __align__(128) float g_O[NB * T_TOK * 4 * CIN];
#define NPAIR (NS * NB * T_TOK * (CIN / 2))
__device__ __align__(128) unsigned g_Qh[NPAIR], g_Ql[NPAIR];
__device__ __align__(128) unsigned g_Kh[NPAIR], g_Kl[NPAIR];
__device__ __align__(128) unsigned g_Vh[NPAIR], g_Vl[NPAIR];

// =================== bf16 2-split helpers ==================================
__device__ __forceinline__ unsigned pack2(float x, float y) {
    __nv_bfloat162 t = __floats2bfloat162_rn(x, y);
    return reinterpret_cast<unsigned&>(t);
}
__device__ __forceinline__ void split_pair(float x, float y, unsigned& h, unsigned& l) {
    float hx = __bfloat162float(__float2bfloat16_rn(x));
    float hy = __bfloat162float(__float2bfloat16_rn(y));
    h = pack2(hx, hy);
    l = pack2(x - hx, y - hy);
}
__device__ __forceinline__ void ldsm4(uint4& r, unsigned addr) {
    asm volatile("ldmatrix.sync.aligned.m8n8.x4.shared.b16 {%0,%1,%2,%3}, [%4];"
                 : "=r"(r.x), "=r"(r.y), "=r"(r.z), "=r"(r.w) : "r"(addr));
}
__device__ __forceinline__ void ldsm4t(uint4& r, unsigned addr) {
    asm volatile("ldmatrix.sync.aligned.m8n8.x4.trans.shared.b16 {%0,%1,%2,%3}, [%4];"
                 : "=r"(r.x), "=r"(r.y), "=r"(r.z), "=r"(r.w) : "r"(addr));
}
__device__ __forceinline__ void cpasync16(unsigned dst, const void* src) {
    asm volatile("cp.async.cg.shared.global [%0], [%1], 16;" :: "r"(dst), "l"(src));
}
__device__ __forceinline__ unsigned smem_u32(const void* p) {
    return (unsigned)__cvta_generic_to_shared(p);
}
__device__ __forceinline__ float fexp2(float x) {
    float y;
    asm("ex2.approx.f32 %0, %1;" : "=f"(y) : "f"(x));
    return y;
}

#define MMA4(C, A, B0, B1)                                                    \
    asm volatile("mma.sync.aligned.m16n8k16.row.col.f32.bf16.bf16.f32 "       \
                 "{%0,%1,%2,%3}, {%4,%5,%6,%7}, {%8,%9}, {%0,%1,%2,%3};"      \
                 : "+f"(C[0]), "+f"(C[1]), "+f"(C[2]), "+f"(C[3])             \
                 : "r"(A.x), "r"(A.y), "r"(A.z), "r"(A.w), "r"(B0), "r"(B1))

#define SQ 36

// ============ tensor-core split GEMM: C[M,N] = A[M,K] @ W[N,K]^T ===========
// BN (eval) folded inline from raw g/b/m/v when bng != nullptr.
#define GEMM_SMEM (384 * SQ * 4)
__global__ void __launch_bounds__(256) gemm_mma(
    const float* __restrict__ A, const float* __restrict__ W,
    int M, int N, int K,
    float* __restrict__ Cf,
    const float* __restrict__ bng, const float* __restrict__ bnb,
    const float* __restrict__ bnm, const float* __restrict__ bnv,
    float* __restrict__ C2, int c2cols)
{
    extern __shared__ unsigned gsm[];
    unsigned* AhS = gsm;
    unsigned* AlS = gsm + 128 * SQ;
    unsigned* WhS = gsm + 256 * SQ;
    unsigned* WlS = gsm + 320 * SQ;

    const int tid = threadIdx.x, lane = tid & 31, warp = tid >> 5;
    const int m0 = blockIdx.y * 128, n0 = blockIdx.x * 64;

    const unsigned sb = smem_u32(gsm);
    const unsigned laneoff =
        (((lane & 7) + ((lane >> 3) & 1) * 8) * SQ + (lane >> 4) * 4) * 4;
    const unsigned aA = sb + (warp * 16 * SQ) * 4 + laneoff;
    const unsigned aAl = aA + 128 * SQ * 4;
    const unsigned aW = sb + (256 * SQ) * 4 + laneoff;
    const unsigned aWl = aW + 64 * SQ * 4;

    float S[8][4] = {};

    for (int k0 = 0; k0 < K; k0 += 64) {
        __syncthreads();
        {
            int row = tid >> 1, half = tid & 1;
            const float* src = A + (size_t)(m0 + row) * K + k0 + half * 32;
            unsigned* dh = AhS + row * SQ + half * 16;
            unsigned* dl = AlS + row * SQ + half * 16;
#pragma unroll
            for (int i = 0; i < 8; i++) {
                float4 v = *(const float4*)(src + i * 4);
                split_pair(v.x, v.y, dh[i * 2], dl[i * 2]);
                split_pair(v.z, v.w, dh[i * 2 + 1], dl[i * 2 + 1]);
            }
        }
        {
            int row = tid >> 2, q = tid & 3;
            const float* src = W + (size_t)(n0 + row) * K + k0 + q * 16;
            unsigned* dh = WhS + row * SQ + q * 8;
            unsigned* dl = WlS + row * SQ + q * 8;
#pragma unroll
            for (int i = 0; i < 4; i++) {
                float4 v = *(const float4*)(src + i * 4);
                split_pair(v.x, v.y, dh[i * 2], dl[i * 2]);
                split_pair(v.z, v.w, dh[i * 2 + 1], dl[i * 2 + 1]);
            }
        }
        __syncthreads();

#pragma unroll
        for (int kk = 0; kk < 4; kk++) {
            uint4 Ah, Al;
            ldsm4(Ah, aA + kk * 32);
            ldsm4(Al, aAl + kk * 32);
#pragma unroll
            for (int jp = 0; jp < 4; jp++) {
                uint4 Bh, Bl;
                ldsm4(Bh, aW + (jp * 16 * SQ) * 4 + kk * 32);
                ldsm4(Bl, aWl + (jp * 16 * SQ) * 4 + kk * 32);
                MMA4(S[2 * jp],     Ah, Bh.x, Bh.z);
                MMA4(S[2 * jp],     Ah, Bl.x, Bl.z);
                MMA4(S[2 * jp],     Al, Bh.x, Bh.z);
                MMA4(S[2 * jp + 1], Ah, Bh.y, Bh.w);
                MMA4(S[2 * jp + 1], Ah, Bl.y, Bl.w);
                MMA4(S[2 * jp + 1], Al, Bh.y, Bh.w);
            }
        }
    }

    const int fr = lane >> 2, fc = lane & 3;
    const int r0 = m0 + warp * 16 + fr;
    const int r1 = r0 + 8;
#pragma unroll
    for (int j = 0; j < 8; j++) {
        int col = n0 + j * 8 + fc * 2;
        float v0 = S[j][0], v1 = S[j][1], v2 = S[j][2], v3 = S[j][3];
        if (bng) {
            float s0 = bng[col] * rsqrtf(bnv[col] + 1e-5f);
            float s1 = bng[col + 1] * rsqrtf(bnv[col + 1] + 1e-5f);
            float b0 = bnb[col] - bnm[col] * s0;
            float b1 = bnb[col + 1] - bnm[col + 1] * s1;
            v0 = v0 * s0 + b0; v1 = v1 * s1 + b1;
            v2 = v2 * s0 + b0; v3 = v3 * s1 + b1;
        }
        *(float2*)(Cf + (size_t)r0 * N + col) = make_float2(v0, v1);
        *(float2*)(Cf + (size_t)r1 * N + col) = make_float2(v2, v3);
        if (C2 && col < c2cols) {
            *(float2*)(C2 + (size_t)r0 * c2cols + col) = make_float2(v0, v1);
            *(float2*)(C2 + (size_t)r1 * c2cols + col) = make_float2(v2, v3);
        }
    }
}

// ============ fused QKV projection (single launch, grid.z selects) =========
__global__ void __launch_bounds__(256) gemm_qkv(
    const float* __restrict__ A,
    const float* __restrict__ Wq, const float* __restrict__ Wk, const float* __restrict__ Wv,
    unsigned* __restrict__ Qh, unsigned* __restrict__ Ql,
    unsigned* __restrict__ Kh, unsigned* __restrict__ Kl,
    unsigned* __restrict__ Vh, unsigned* __restrict__ Vl)
{
    extern __shared__ unsigned gsm[];
    unsigned* AhS = gsm;
    unsigned* AlS = gsm + 128 * SQ;
    unsigned* WhS = gsm + 256 * SQ;
    unsigned* WlS = gsm + 320 * SQ;

    const int tid = threadIdx.x, lane = tid & 31, warp = tid >> 5;
    const int m0 = blockIdx.y * 128, n0 = blockIdx.x * 64;
    const int z = blockIdx.z;
    const float* W = (z == 0) ? Wq : (z == 1) ? Wk : Wv;
    unsigned* Chi = (z == 0) ? Qh : (z == 1) ? Kh : Vh;
    unsigned* Clo = (z == 0) ? Ql : (z == 1) ? Kl : Vl;
    const float mult = (z == 0) ? 1.4426950408889634f : 1.0f;
    const int K = C4, N = CIN;

    const unsigned sb = smem_u32(gsm);
    const unsigned laneoff =
        (((lane & 7) + ((lane >> 3) & 1) * 8) * SQ + (lane >> 4) * 4) * 4;
    const unsigned aA = sb + (warp * 16 * SQ) * 4 + laneoff;
    const unsigned aAl = aA + 128 * SQ * 4;
    const unsigned aW = sb + (256 * SQ) * 4 + laneoff;
    const unsigned aWl = aW + 64 * SQ * 4;

    float S[8][4] = {};

    {
        int row = tid >> 1, half = tid & 1;
        const float* src = A + (size_t)(m0 + row) * K + half * 32;
        unsigned* dh = AhS + row * SQ + half * 16;
        unsigned* dl = AlS + row * SQ + half * 16;
#pragma unroll
        for (int i = 0; i < 8; i++) {
            float4 v = *(const float4*)(src + i * 4);
            split_pair(v.x, v.y, dh[i * 2], dl[i * 2]);
            split_pair(v.z, v.w, dh[i * 2 + 1], dl[i * 2 + 1]);
        }
    }
    {
        int row = tid >> 2, q = tid & 3;
        const float* src = W + (size_t)(n0 + row) * K + q * 16;
        unsigned* dh = WhS + row * SQ + q * 8;
        unsigned* dl = WlS + row * SQ + q * 8;
#pragma unroll
        for (int i = 0; i < 4; i++) {
            float4 v = *(const float4*)(src + i * 4);
            split_pair(v.x, v.y, dh[i * 2], dl[i * 2]);
            split_pair(v.z, v.w, dh[i * 2 + 1], dl[i * 2 + 1]);
        }
    }
    __syncthreads();

#pragma unroll
    for (int kk = 0; kk < 4; kk++) {
        uint4 Ah, Al;
        ldsm4(Ah, aA + kk * 32);
        ldsm4(Al, aAl + kk * 32);
#pragma unroll
        for (int jp = 0; jp < 4; jp++) {
            uint4 Bh, Bl;
            ldsm4(Bh, aW + (jp * 16 * SQ) * 4 + kk * 32);
            ldsm4(Bl, aWl + (jp * 16 * SQ) * 4 + kk * 32);
            MMA4(S[2 * jp],     Ah, Bh.x, Bh.z);
            MMA4(S[2 * jp],     Ah, Bl.x, Bl.z);
            MMA4(S[2 * jp],     Al, Bh.x, Bh.z);
            MMA4(S[2 * jp + 1], Ah, Bh.y, Bh.w);
            MMA4(S[2 * jp + 1], Ah, Bl.y, Bl.w);
            MMA4(S[2 * jp + 1], Al, Bh.y, Bh.w);
        }
    }

    const int fr = lane >> 2, fc = lane & 3;
    const int r0 = m0 + warp * 16 + fr;
    const int r1 = r0 + 8;
#pragma unroll
    for (int j = 0; j < 8; j++) {
        int col = n0 + j * 8 + fc * 2;
        float v0 = S[j][0] * mult, v1 = S[j][1] * mult;
        float v2 = S[j][2] * mult, v3 = S[j][3] * mult;
        unsigned h0, l0, h1, l1;
        split_pair(v0, v1, h0, l0);
        split_pair(v2, v3, h1, l1);
        int ci = col >> 1, nw = N >> 1;
        Chi[(size_t)r0 * nw + ci] = h0; Clo[(size_t)r0 * nw + ci] = l0;
        Chi[(size_t)r1 * nw + ci] = h1; Clo[(size_t)r1 * nw + ci] = l1;
    }
}

// ============ fused depthwise 3x3 + pointwise 1x1 + BN2 (8-token blocks) ===
// grid 576, 256 threads. thread: token lt = tid>>5, 2 channels {ol, ol+32}.
__global__ void __launch_bounds__(256) dwpw8(
    const float* __restrict__ ident, const float* __restrict__ Rprev,
    const float* __restrict__ dw, const float* __restrict__ pw,
    const float* __restrict__ bn2g, const float* __restrict__ bn2b,
    const float* __restrict__ bn2m, const float* __restrict__ bn2v,
    float* __restrict__ Rout, int s)
{
    __shared__ float Ws[64 * 65];   // [c][o], stride 65 (conflict-free)
    __shared__ float Ds[8 * 68];    // [lt][c]
    __shared__ float wsm[C4 * 9];
    const int tid = threadIdx.x;

    // stage pw transposed: pw[o][c] -> Ws[c*65+o]; coalesced reads
#pragma unroll
    for (int k = 0; k < 16; k++) {
        int idx = tid + k * 256;
        int oo = idx >> 6, cc = idx & 63;
        Ws[cc * 65 + oo] = pw[idx];
    }
    for (int i = tid; i < C4 * 9; i += 256) wsm[i] = dw[i];
    __syncthreads();   // <-- the missing barrier (round-9 bug): wsm/Ws visible

    const int lt = tid >> 5;            // 0..7 token in block
    const int ol = tid & 31;            // channel base
    const int g = blockIdx.x * 8 + lt;
    const int b = g / T_TOK, t = g - b * T_TOK;
    const int hh = t / WW, ww = t % WW;

    // dw phase: this thread computes D[lt][ol] and D[lt][ol+32]
    {
        const float* ib = ident + (size_t)b * T_TOK * CIN + s * C4;
        const float* rb = Rprev ? (Rprev + (size_t)b * T_TOK * C4) : nullptr;
        float a0 = 0.f, a1 = 0.f;
        const int c0 = ol, c1 = ol + 32;
#pragma unroll
        for (int kh = 0; kh < 3; kh++) {
            int h2 = hh + kh - 1;
            if ((unsigned)h2 >= HH) continue;
#pragma unroll
            for (int kw = 0; kw < 3; kw++) {
                int w2 = ww + kw - 1;
                if ((unsigned)w2 >= WW) continue;
                int tt = h2 * WW + w2;
                float v0 = ib[(size_t)tt * CIN + c0];
                float v1 = ib[(size_t)tt * CIN + c1];
                if (rb) {
                    v0 += rb[(size_t)tt * C4 + c0];
                    v1 += rb[(size_t)tt * C4 + c1];
                }
                a0 += v0 * wsm[c0 * 9 + kh * 3 + kw];
                a1 += v1 * wsm[c1 * 9 + kh * 3 + kw];
            }
        }
        Ds[lt * 68 + c0] = a0;
        Ds[lt * 68 + c1] = a1;
    }
    __syncthreads();

    // dot: out[g][o] for o in {ol, ol+32}
    float acc0 = 0.f, acc1 = 0.f;
#pragma unroll 16
    for (int c = 0; c < 64; c++) {
        float d = Ds[lt * 68 + c];                 // warp-broadcast
        acc0 += d * Ws[c * 65 + ol];
        acc1 += d * Ws[c * 65 + ol + 32];
    }
    {
        float sc0 = bn2g[ol] * rsqrtf(bn2v[ol] + 1e-5f);
        float bi0 = bn2b[ol] - bn2m[ol] * sc0;
        float sc1 = bn2g[ol + 32] * rsqrtf(bn2v[ol + 32] + 1e-5f);
        float bi1 = bn2b[ol + 32] - bn2m[ol + 32] * sc1;
        Rout[(size_t)g * C4 + ol]      = acc0 * sc0 + bi0;
        Rout[(size_t)g * C4 + ol + 32] = acc1 * sc1 + bi1;
    }
}

// ================= tensor-core flash attention =============================
// 8 warps, Q-tile 128, K-tile 64; cp.async double-buffered K/V; fixed-max
// softmax (Q pre-scaled by log2e -> ex2); V via ldmatrix.trans.
// Q fragments hoisted into registers (loop-invariant).
#define AT_SMEM (27648 * 4)    // 110592 B -> 2 CTAs/SM
__global__ void __launch_bounds__(256, 2) attn5(
    const unsigned* __restrict__ Qhg, const unsigned* __restrict__ Qlg,
    const unsigned* __restrict__ Khg, const unsigned* __restrict__ Klg,
    const unsigned* __restrict__ Vhg, const unsigned* __restrict__ Vlg,
    float* __restrict__ O)
{
    extern __shared__ unsigned smu[];
    unsigned* QhS = smu;
    unsigned* QlS = smu + 128 * SQ;

    const int tid = threadIdx.x, lane = tid & 31, warp = tid >> 5;
    const int y = blockIdx.y;
    const int s = y >> 3, b = (y >> 2) & 1, h = y & 3;
    const int t0 = blockIdx.x * 128;
    const size_t row0 = (size_t)(s * NB + b) * T_TOK;

    const unsigned sb = smem_u32(smu);
    const unsigned laneoff =
        (((lane & 7) + ((lane >> 3) & 1) * 8) * SQ + (lane >> 4) * 4) * 4;

    // ---- stage Q (once), then load fragments into registers ----
    {
        int row = tid >> 1, off = (tid & 1) * 16;
        const uint4* sH = (const uint4*)(Qhg + (row0 + t0 + row) * 128 + h * 32 + off);
        const uint4* sL = (const uint4*)(Qlg + (row0 + t0 + row) * 128 + h * 32 + off);
        uint4* dH = (uint4*)(QhS + row * SQ + off);
        uint4* dL = (uint4*)(QlS + row * SQ + off);
#pragma unroll
        for (int i = 0; i < 4; i++) { dH[i] = sH[i]; dL[i] = sL[i]; }
    }
    __syncthreads();

    const unsigned aQh = sb + (warp * 16 * SQ) * 4 + laneoff;
    const unsigned aQl = aQh + 128 * SQ * 4;
    uint4 QfH[4], QfL[4];
#pragma unroll
    for (int kk = 0; kk < 4; kk++) {
        ldsm4(QfH[kk], aQh + kk * 32);
        ldsm4(QfL[kk], aQl + kk * 32);
    }

    const int fr = lane >> 2, fc = lane & 3;
    const int qr = warp * 16 + fr;

    const int srow = tid >> 2, soff = (tid & 3) * 8;
    auto issue_stage = [&](int st, int kb) {
        size_t kg = (row0 + (size_t)kb * 64 + srow) * 128 + h * 32 + soff;
        unsigned base = sb + (9216 + st * 9216 + srow * SQ + soff) * 4;
        cpasync16(base,                 Khg + kg);
        cpasync16(base + 16,            Khg + kg + 4);
        cpasync16(base + 2304 * 4,      Klg + kg);
        cpasync16(base + 2304 * 4 + 16, Klg + kg + 4);
        cpasync16(base + 4608 * 4,      Vhg + kg);
        cpasync16(base + 4608 * 4 + 16, Vhg + kg + 4);
        cpasync16(base + 6912 * 4,      Vlg + kg);
        cpasync16(base + 6912 * 4 + 16, Vlg + kg + 4);
    };

    float Ov[8][4] = {};
    float l0s = 0.f, l1s = 0.f;

    issue_stage(0, 0);
    asm volatile("cp.async.commit_group;");

    for (int kb = 0; kb < T_TOK / 64; kb++) {
        const int cur = kb & 1;
        if (kb + 1 < T_TOK / 64) {
            issue_stage(cur ^ 1, kb + 1);
            asm volatile("cp.async.commit_group;");
            asm volatile("cp.async.wait_group 1;");
        } else {
            asm volatile("cp.async.wait_group 0;");
        }
        __syncthreads();

        const unsigned bstg = sb + (9216 + cur * 9216) * 4 + laneoff;
        const unsigned aKh = bstg;
        const unsigned aKl = bstg + 2304 * 4;
        const unsigned aVh = bstg + 4608 * 4;
        const unsigned aVl = bstg + 6912 * 4;

        // ---- S = Q K^T : 16x64 per warp ----
        float S[8][4];
#pragma unroll
        for (int j = 0; j < 8; j++)
            S[j][0] = S[j][1] = S[j][2] = S[j][3] = 0.f;

#pragma unroll
        for (int kk = 0; kk < 4; kk++) {
#pragma unroll
            for (int jp = 0; jp < 4; jp++) {
                uint4 Bh, Bl;
                ldsm4(Bh, aKh + (jp * 16 * SQ) * 4 + kk * 32);
                ldsm4(Bl, aKl + (jp * 16 * SQ) * 4 + kk * 32);
                MMA4(S[2 * jp],     QfH[kk], Bh.x, Bh.z);
                MMA4(S[2 * jp],     QfH[kk], Bl.x, Bl.z);
                MMA4(S[2 * jp],     QfL[kk], Bh.x, Bh.z);
                MMA4(S[2 * jp + 1], QfH[kk], Bh.y, Bh.w);
                MMA4(S[2 * jp + 1], QfH[kk], Bl.y, Bl.w);
                MMA4(S[2 * jp + 1], QfL[kk], Bh.y, Bh.w);
            }
        }

        // ---- softmax (fixed max 0; ex2) + PV ----
#pragma unroll
        for (int kk = 0; kk < 4; kk++) {
            const int j0 = 2 * kk, j1 = 2 * kk + 1;
            float p00 = fexp2(S[j0][0]), p01 = fexp2(S[j0][1]);
            float p02 = fexp2(S[j0][2]), p03 = fexp2(S[j0][3]);
            float p10 = fexp2(S[j1][0]), p11 = fexp2(S[j1][1]);
            float p12 = fexp2(S[j1][2]), p13 = fexp2(S[j1][3]);
            l0s += (p00 + p01) + (p10 + p11);
            l1s += (p02 + p03) + (p12 + p13);
            uint4 Ph, Pl;
            split_pair(p00, p01, Ph.x, Pl.x);
            split_pair(p02, p03, Ph.y, Pl.y);
            split_pair(p10, p11, Ph.z, Pl.z);
            split_pair(p12, p13, Ph.w, Pl.w);
#pragma unroll
            for (int jp = 0; jp < 4; jp++) {
                uint4 Bh, Bl;
                ldsm4t(Bh, aVh + (kk * 16 * SQ) * 4 + jp * 32);
                ldsm4t(Bl, aVl + (kk * 16 * SQ) * 4 + jp * 32);
                MMA4(Ov[2 * jp],     Ph, Bh.x, Bh.y);
                MMA4(Ov[2 * jp],     Ph, Bl.x, Bl.y);
                MMA4(Ov[2 * jp],     Pl, Bh.x, Bh.y);
                MMA4(Ov[2 * jp + 1], Ph, Bh.z, Bh.w);
                MMA4(Ov[2 * jp + 1], Ph, Bl.z, Bl.w);
                MMA4(Ov[2 * jp + 1], Pl, Bh.z, Bh.w);
            }
        }
        __syncthreads();
    }

    // ---- epilogue: reduce l over the quad, normalize, store ----
    l0s += __shfl_xor_sync(0xffffffffu, l0s, 1);
    l0s += __shfl_xor_sync(0xffffffffu, l0s, 2);
    l1s += __shfl_xor_sync(0xffffffffu, l1s, 1);
    l1s += __shfl_xor_sync(0xffffffffu, l1s, 2);
    float inv0 = 1.0f / l0s, inv1 = 1.0f / l1s;
    const size_t feat0 = (size_t)s * CIN + h * DH;
    const size_t r0g = (size_t)b * T_TOK + t0 + qr;
    const size_t r1g = r0g + 8;
#pragma unroll
    for (int j = 0; j < 8; j++) {
        size_t col = feat0 + j * 8 + fc * 2;
        *(float2*)(O + r0g * (4 * CIN) + col) = make_float2(Ov[j][0] * inv0, Ov[j][1] * inv0);
        *(float2*)(O + r1g * (4 * CIN) + col) = make_float2(Ov[j][2] * inv1, Ov[j][3] * inv1);
    }
}

// ---------------------------------------------------------------------------
extern "C" void kernel_launch(void* const* d_in, const int* in_sizes, int n_in,
                              void* d_out, int out_size)
{
    const float* x    = (const float*)d_in[0];
    const float* w1   = (const float*)d_in[1];
    const float* bn1g = (const float*)d_in[2];
    const float* bn1b = (const float*)d_in[3];
    const float* bn1m = (const float*)d_in[4];
    const float* bn1v = (const float*)d_in[5];
    const float* dww  = (const float*)d_in[6];
    const float* pww  = (const float*)d_in[7];
    const float* bn2g = (const float*)d_in[8];
    const float* bn2b = (const float*)d_in[9];
    const float* bn2m = (const float*)d_in[10];
    const float* bn2v = (const float*)d_in[11];
    const float* Wq   = (const float*)d_in[12];
    const float* Wk   = (const float*)d_in[13];
    const float* Wv   = (const float*)d_in[14];
    const float* Wout = (const float*)d_in[15];
    float* out = (float*)d_out;

    void* p;
    cudaGetSymbolAddress(&p, g_identity); float* ident = (float*)p;
    cudaGetSymbolAddress(&p, g_R);        float* Rp    = (float*)p;
    cudaGetSymbolAddress(&p, g_O);        float* Op    = (float*)p;
    cudaGetSymbolAddress(&p, g_Qh);  unsigned* Qh = (unsigned*)p;
    cudaGetSymbolAddress(&p, g_Ql);  unsigned* Ql = (unsigned*)p;
    cudaGetSymbolAddress(&p, g_Kh);  unsigned* Kh = (unsigned*)p;
    cudaGetSymbolAddress(&p, g_Kl);  unsigned* Kl = (unsigned*)p;
    cudaGetSymbolAddress(&p, g_Vh);  unsigned* Vh = (unsigned*)p;
    cudaGetSymbolAddress(&p, g_Vl);  unsigned* Vl = (unsigned*)p;

    cudaFuncSetAttribute(gemm_mma, cudaFuncAttributeMaxDynamicSharedMemorySize, GEMM_SMEM);
    cudaFuncSetAttribute(gemm_qkv, cudaFuncAttributeMaxDynamicSharedMemorySize, GEMM_SMEM);
    cudaFuncSetAttribute(attn5, cudaFuncAttributeMaxDynamicSharedMemorySize, AT_SMEM);

    // [0] conv_in + BN1 (inline) -> identity ; channels [0,64) also into R[0]
    gemm_mma<<<dim3(4, 36), 256, GEMM_SMEM>>>(
        x, w1, NB * T_TOK, CIN, CIN, ident, bn1g, bn1b, bn1m, bn1v, Rp, C4);

    // [1..3] Res2Net scales (fused dw+pw+BN2, 8-token blocks, grid 576)
    for (int s = 1; s <= 3; s++) {
        const float* prev = (s == 1) ? nullptr : (Rp + (size_t)(s - 1) * NB * T_TOK * C4);
        dwpw8<<<(NB * T_TOK) / 8, 256>>>(
            ident, prev, dww, pww, bn2g, bn2b, bn2m, bn2v,
            Rp + (size_t)s * NB * T_TOK * C4, s);
    }

    // [4] fused Q/K/V projections -> pre-split hi/lo (Q scaled by log2e)
    gemm_qkv<<<dim3(4, 144, 3), 256, GEMM_SMEM>>>(
        Rp, Wq, Wk, Wv, Qh, Ql, Kh, Kl, Vh, Vl);

    // [5] flash attention
    attn5<<<dim3(T_TOK / 128, NS * NB * NH), 256, AT_SMEM>>>(
        Qh, Ql, Kh, Kl, Vh, Vl, Op);

    // [6] output projection -> d_out
    gemm_mma<<<dim3(4, 36), 256, GEMM_SMEM>>>(
        Op, Wout, NB * T_TOK, CIN, 4 * CIN, out,
        nullptr, nullptr, nullptr, nullptr, nullptr, 0);
}

// round 11
// speedup vs baseline: 1.2024x; 1.0405x over previous
#include <cuda_runtime.h>
#include <cuda_bf16.h>

// Problem constants (fixed shapes)
#define T_TOK 2304
#define NB    2
#define CIN   256
#define C4    64
#define NS    4
#define NH    4
#define DH    64
#define HH    48
#define WW    48

// ---------------- scratch (device globals; no allocation allowed) ----------
__device__ __align__(128) float g_identity[NB * T_TOK * CIN];
__device__ __align__(128) float g_R[NS * NB * T_TOK * C4];
__device__ __align__(128) float g_O[NB * T_TOK * 4 * CIN];
#define NPAIR (NS * NB * T_TOK * (CIN / 2))
__device__ __align__(128) unsigned g_Qh[NPAIR], g_Ql[NPAIR];
__device__ __align__(128) unsigned g_Kh[NPAIR], g_Kl[NPAIR];
__device__ __align__(128) unsigned g_Vh[NPAIR], g_Vl[NPAIR];

// =================== bf16 2-split helpers ==================================
__device__ __forceinline__ unsigned pack2(float x, float y) {
    __nv_bfloat162 t = __floats2bfloat162_rn(x, y);
    return reinterpret_cast<unsigned&>(t);
}
__device__ __forceinline__ void split_pair(float x, float y, unsigned& h, unsigned& l) {
    float hx = __bfloat162float(__float2bfloat16_rn(x));
    float hy = __bfloat162float(__float2bfloat16_rn(y));
    h = pack2(hx, hy);
    l = pack2(x - hx, y - hy);
}
// truncation split for positive P values: hi = trunc16(p), lo = p - hi (exact)
__device__ __forceinline__ unsigned prmt_hi(unsigned a, unsigned b) {
    unsigned r;
    asm("prmt.b32 %0, %1, %2, 0x7632;" : "=r"(r) : "r"(a), "r"(b));
    return r;
}
__device__ __forceinline__ void ldsm4(uint4& r, unsigned addr) {
    asm volatile("ldmatrix.sync.aligned.m8n8.x4.shared.b16 {%0,%1,%2,%3}, [%4];"
                 : "=r"(r.x), "=r"(r.y), "=r"(r.z), "=r"(r.w) : "r"(addr));
}
__device__ __forceinline__ void ldsm4t(uint4& r, unsigned addr) {
    asm volatile("ldmatrix.sync.aligned.m8n8.x4.trans.shared.b16 {%0,%1,%2,%3}, [%4];"
                 : "=r"(r.x), "=r"(r.y), "=r"(r.z), "=r"(r.w) : "r"(addr));
}
__device__ __forceinline__ void cpasync16(unsigned dst, const void* src) {
    asm volatile("cp.async.cg.shared.global [%0], [%1], 16;" :: "r"(dst), "l"(src));
}
__device__ __forceinline__ unsigned smem_u32(const void* p) {
    return (unsigned)__cvta_generic_to_shared(p);
}
__device__ __forceinline__ float fexp2(float x) {
    float y;
    asm("ex2.approx.f32 %0, %1;" : "=f"(y) : "f"(x));
    return y;
}

#define MMA4(C, A, B0, B1)                                                    \
    asm volatile("mma.sync.aligned.m16n8k16.row.col.f32.bf16.bf16.f32 "       \
                 "{%0,%1,%2,%3}, {%4,%5,%6,%7}, {%8,%9}, {%0,%1,%2,%3};"      \
                 : "+f"(C[0]), "+f"(C[1]), "+f"(C[2]), "+f"(C[3])             \
                 : "r"(A.x), "r"(A.y), "r"(A.z), "r"(A.w), "r"(B0), "r"(B1))

#define SQ 36

// ============ tensor-core split GEMM: C[M,N] = A[M,K] @ W[N,K]^T ===========
// BN (eval) folded inline from raw g/b/m/v when bng != nullptr.
#define GEMM_SMEM (384 * SQ * 4)
__global__ void __launch_bounds__(256) gemm_mma(
    const float* __restrict__ A, const float* __restrict__ W,
    int M, int N, int K,
    float* __restrict__ Cf,
    const float* __restrict__ bng, const float* __restrict__ bnb,
    const float* __restrict__ bnm, const float* __restrict__ bnv,
    float* __restrict__ C2, int c2cols)
{
    extern __shared__ unsigned gsm[];
    unsigned* AhS = gsm;
    unsigned* AlS = gsm + 128 * SQ;
    unsigned* WhS = gsm + 256 * SQ;
    unsigned* WlS = gsm + 320 * SQ;

    const int tid = threadIdx.x, lane = tid & 31, warp = tid >> 5;
    const int m0 = blockIdx.y * 128, n0 = blockIdx.x * 64;

    const unsigned sb = smem_u32(gsm);
    const unsigned laneoff =
        (((lane & 7) + ((lane >> 3) & 1) * 8) * SQ + (lane >> 4) * 4) * 4;
    const unsigned aA = sb + (warp * 16 * SQ) * 4 + laneoff;
    const unsigned aAl = aA + 128 * SQ * 4;
    const unsigned aW = sb + (256 * SQ) * 4 + laneoff;
    const unsigned aWl = aW + 64 * SQ * 4;

    float S[8][4] = {};

    for (int k0 = 0; k0 < K; k0 += 64) {
        __syncthreads();
        {
            int row = tid >> 1, half = tid & 1;
            const float* src = A + (size_t)(m0 + row) * K + k0 + half * 32;
            unsigned* dh = AhS + row * SQ + half * 16;
            unsigned* dl = AlS + row * SQ + half * 16;
#pragma unroll
            for (int i = 0; i < 8; i++) {
                float4 v = *(const float4*)(src + i * 4);
                split_pair(v.x, v.y, dh[i * 2], dl[i * 2]);
                split_pair(v.z, v.w, dh[i * 2 + 1], dl[i * 2 + 1]);
            }
        }
        {
            int row = tid >> 2, q = tid & 3;
            const float* src = W + (size_t)(n0 + row) * K + k0 + q * 16;
            unsigned* dh = WhS + row * SQ + q * 8;
            unsigned* dl = WlS + row * SQ + q * 8;
#pragma unroll
            for (int i = 0; i < 4; i++) {
                float4 v = *(const float4*)(src + i * 4);
                split_pair(v.x, v.y, dh[i * 2], dl[i * 2]);
                split_pair(v.z, v.w, dh[i * 2 + 1], dl[i * 2 + 1]);
            }
        }
        __syncthreads();

#pragma unroll
        for (int kk = 0; kk < 4; kk++) {
            uint4 Ah, Al;
            ldsm4(Ah, aA + kk * 32);
            ldsm4(Al, aAl + kk * 32);
#pragma unroll
            for (int jp = 0; jp < 4; jp++) {
                uint4 Bh, Bl;
                ldsm4(Bh, aW + (jp * 16 * SQ) * 4 + kk * 32);
                ldsm4(Bl, aWl + (jp * 16 * SQ) * 4 + kk * 32);
                MMA4(S[2 * jp],     Ah, Bh.x, Bh.z);
                MMA4(S[2 * jp],     Ah, Bl.x, Bl.z);
                MMA4(S[2 * jp],     Al, Bh.x, Bh.z);
                MMA4(S[2 * jp + 1], Ah, Bh.y, Bh.w);
                MMA4(S[2 * jp + 1], Ah, Bl.y, Bl.w);
                MMA4(S[2 * jp + 1], Al, Bh.y, Bh.w);
            }
        }
    }

    const int fr = lane >> 2, fc = lane & 3;
    const int r0 = m0 + warp * 16 + fr;
    const int r1 = r0 + 8;
#pragma unroll
    for (int j = 0; j < 8; j++) {
        int col = n0 + j * 8 + fc * 2;
        float v0 = S[j][0], v1 = S[j][1], v2 = S[j][2], v3 = S[j][3];
        if (bng) {
            float s0 = bng[col] * rsqrtf(bnv[col] + 1e-5f);
            float s1 = bng[col + 1] * rsqrtf(bnv[col + 1] + 1e-5f);
            float b0 = bnb[col] - bnm[col] * s0;
            float b1 = bnb[col + 1] - bnm[col + 1] * s1;
            v0 = v0 * s0 + b0; v1 = v1 * s1 + b1;
            v2 = v2 * s0 + b0; v3 = v3 * s1 + b1;
        }
        *(float2*)(Cf + (size_t)r0 * N + col) = make_float2(v0, v1);
        *(float2*)(Cf + (size_t)r1 * N + col) = make_float2(v2, v3);
        if (C2 && col < c2cols) {
            *(float2*)(C2 + (size_t)r0 * c2cols + col) = make_float2(v0, v1);
            *(float2*)(C2 + (size_t)r1 * c2cols + col) = make_float2(v2, v3);
        }
    }
}

// ============ fused QKV projection (single launch, grid.z selects) =========
__global__ void __launch_bounds__(256) gemm_qkv(
    const float* __restrict__ A,
    const float* __restrict__ Wq, const float* __restrict__ Wk, const float* __restrict__ Wv,
    unsigned* __restrict__ Qh, unsigned* __restrict__ Ql,
    unsigned* __restrict__ Kh, unsigned* __restrict__ Kl,
    unsigned* __restrict__ Vh, unsigned* __restrict__ Vl)
{
    extern __shared__ unsigned gsm[];
    unsigned* AhS = gsm;
    unsigned* AlS = gsm + 128 * SQ;
    unsigned* WhS = gsm + 256 * SQ;
    unsigned* WlS = gsm + 320 * SQ;

    const int tid = threadIdx.x, lane = tid & 31, warp = tid >> 5;
    const int m0 = blockIdx.y * 128, n0 = blockIdx.x * 64;
    const int z = blockIdx.z;
    const float* W = (z == 0) ? Wq : (z == 1) ? Wk : Wv;
    unsigned* Chi = (z == 0) ? Qh : (z == 1) ? Kh : Vh;
    unsigned* Clo = (z == 0) ? Ql : (z == 1) ? Kl : Vl;
    const float mult = (z == 0) ? 1.4426950408889634f : 1.0f;
    const int K = C4, N = CIN;

    const unsigned sb = smem_u32(gsm);
    const unsigned laneoff =
        (((lane & 7) + ((lane >> 3) & 1) * 8) * SQ + (lane >> 4) * 4) * 4;
    const unsigned aA = sb + (warp * 16 * SQ) * 4 + laneoff;
    const unsigned aAl = aA + 128 * SQ * 4;
    const unsigned aW = sb + (256 * SQ) * 4 + laneoff;
    const unsigned aWl = aW + 64 * SQ * 4;

    float S[8][4] = {};

    {
        int row = tid >> 1, half = tid & 1;
        const float* src = A + (size_t)(m0 + row) * K + half * 32;
        unsigned* dh = AhS + row * SQ + half * 16;
        unsigned* dl = AlS + row * SQ + half * 16;
#pragma unroll
        for (int i = 0; i < 8; i++) {
            float4 v = *(const float4*)(src + i * 4);
            split_pair(v.x, v.y, dh[i * 2], dl[i * 2]);
            split_pair(v.z, v.w, dh[i * 2 + 1], dl[i * 2 + 1]);
        }
    }
    {
        int row = tid >> 2, q = tid & 3;
        const float* src = W + (size_t)(n0 + row) * K + q * 16;
        unsigned* dh = WhS + row * SQ + q * 8;
        unsigned* dl = WlS + row * SQ + q * 8;
#pragma unroll
        for (int i = 0; i < 4; i++) {
            float4 v = *(const float4*)(src + i * 4);
            split_pair(v.x, v.y, dh[i * 2], dl[i * 2]);
            split_pair(v.z, v.w, dh[i * 2 + 1], dl[i * 2 + 1]);
        }
    }
    __syncthreads();

#pragma unroll
    for (int kk = 0; kk < 4; kk++) {
        uint4 Ah, Al;
        ldsm4(Ah, aA + kk * 32);
        ldsm4(Al, aAl + kk * 32);
#pragma unroll
        for (int jp = 0; jp < 4; jp++) {
            uint4 Bh, Bl;
            ldsm4(Bh, aW + (jp * 16 * SQ) * 4 + kk * 32);
            ldsm4(Bl, aWl + (jp * 16 * SQ) * 4 + kk * 32);
            MMA4(S[2 * jp],     Ah, Bh.x, Bh.z);
            MMA4(S[2 * jp],     Ah, Bl.x, Bl.z);
            MMA4(S[2 * jp],     Al, Bh.x, Bh.z);
            MMA4(S[2 * jp + 1], Ah, Bh.y, Bh.w);
            MMA4(S[2 * jp + 1], Ah, Bl.y, Bl.w);
            MMA4(S[2 * jp + 1], Al, Bh.y, Bh.w);
        }
    }

    const int fr = lane >> 2, fc = lane & 3;
    const int r0 = m0 + warp * 16 + fr;
    const int r1 = r0 + 8;
#pragma unroll
    for (int j = 0; j < 8; j++) {
        int col = n0 + j * 8 + fc * 2;
        float v0 = S[j][0] * mult, v1 = S[j][1] * mult;
        float v2 = S[j][2] * mult, v3 = S[j][3] * mult;
        unsigned h0, l0, h1, l1;
        split_pair(v0, v1, h0, l0);
        split_pair(v2, v3, h1, l1);
        int ci = col >> 1, nw = N >> 1;
        Chi[(size_t)r0 * nw + ci] = h0; Clo[(size_t)r0 * nw + ci] = l0;
        Chi[(size_t)r1 * nw + ci] = h1; Clo[(size_t)r1 * nw + ci] = l1;
    }
}

// ============ fused depthwise 3x3 + pointwise 1x1 + BN2 (8-token blocks) ===
__global__ void __launch_bounds__(256) dwpw8(
    const float* __restrict__ ident, const float* __restrict__ Rprev,
    const float* __restrict__ dw, const float* __restrict__ pw,
    const float* __restrict__ bn2g, const float* __restrict__ bn2b,
    const float* __restrict__ bn2m, const float* __restrict__ bn2v,
    float* __restrict__ Rout, int s)
{
    __shared__ float Ws[64 * 65];
    __shared__ float Ds[8 * 68];
    __shared__ float wsm[C4 * 9];
    const int tid = threadIdx.x;

#pragma unroll
    for (int k = 0; k < 16; k++) {
        int idx = tid + k * 256;
        int oo = idx >> 6, cc = idx & 63;
        Ws[cc * 65 + oo] = pw[idx];
    }
    for (int i = tid; i < C4 * 9; i += 256) wsm[i] = dw[i];
    __syncthreads();

    const int lt = tid >> 5;
    const int ol = tid & 31;
    const int g = blockIdx.x * 8 + lt;
    const int b = g / T_TOK, t = g - b * T_TOK;
    const int hh = t / WW, ww = t % WW;

    {
        const float* ib = ident + (size_t)b * T_TOK * CIN + s * C4;
        const float* rb = Rprev ? (Rprev + (size_t)b * T_TOK * C4) : nullptr;
        float a0 = 0.f, a1 = 0.f;
        const int c0 = ol, c1 = ol + 32;
#pragma unroll
        for (int kh = 0; kh < 3; kh++) {
            int h2 = hh + kh - 1;
            if ((unsigned)h2 >= HH) continue;
#pragma unroll
            for (int kw = 0; kw < 3; kw++) {
                int w2 = ww + kw - 1;
                if ((unsigned)w2 >= WW) continue;
                int tt = h2 * WW + w2;
                float v0 = ib[(size_t)tt * CIN + c0];
                float v1 = ib[(size_t)tt * CIN + c1];
                if (rb) {
                    v0 += rb[(size_t)tt * C4 + c0];
                    v1 += rb[(size_t)tt * C4 + c1];
                }
                a0 += v0 * wsm[c0 * 9 + kh * 3 + kw];
                a1 += v1 * wsm[c1 * 9 + kh * 3 + kw];
            }
        }
        Ds[lt * 68 + c0] = a0;
        Ds[lt * 68 + c1] = a1;
    }
    __syncthreads();

    float acc0 = 0.f, acc1 = 0.f;
#pragma unroll 16
    for (int c = 0; c < 64; c++) {
        float d = Ds[lt * 68 + c];
        acc0 += d * Ws[c * 65 + ol];
        acc1 += d * Ws[c * 65 + ol + 32];
    }
    {
        float sc0 = bn2g[ol] * rsqrtf(bn2v[ol] + 1e-5f);
        float bi0 = bn2b[ol] - bn2m[ol] * sc0;
        float sc1 = bn2g[ol + 32] * rsqrtf(bn2v[ol + 32] + 1e-5f);
        float bi1 = bn2b[ol + 32] - bn2m[ol + 32] * sc1;
        Rout[(size_t)g * C4 + ol]      = acc0 * sc0 + bi0;
        Rout[(size_t)g * C4 + ol + 32] = acc1 * sc1 + bi1;
    }
}

// ================= tensor-core flash attention =============================
// 8 warps, Q-tile 128, K-tile 64; cp.async double-buffered K/V; fixed-max
// softmax (Q pre-scaled by log2e -> ex2); V via ldmatrix.trans.
// Q ldsm in-loop (hoist reverted: register pressure caused spills).
// P split via truncation (LOP/FSUB/PRMT, no CVT-pipe traffic).
#define AT_SMEM (27648 * 4)    // 110592 B -> 2 CTAs/SM
__global__ void __launch_bounds__(256, 2) attn5(
    const unsigned* __restrict__ Qhg, const unsigned* __restrict__ Qlg,
    const unsigned* __restrict__ Khg, const unsigned* __restrict__ Klg,
    const unsigned* __restrict__ Vhg, const unsigned* __restrict__ Vlg,
    float* __restrict__ O)
{
    extern __shared__ unsigned smu[];
    unsigned* QhS = smu;
    unsigned* QlS = smu + 128 * SQ;

    const int tid = threadIdx.x, lane = tid & 31, warp = tid >> 5;
    const int y = blockIdx.y;
    const int s = y >> 3, b = (y >> 2) & 1, h = y & 3;
    const int t0 = blockIdx.x * 128;
    const size_t row0 = (size_t)(s * NB + b) * T_TOK;

    const unsigned sb = smem_u32(smu);
    const unsigned laneoff =
        (((lane & 7) + ((lane >> 3) & 1) * 8) * SQ + (lane >> 4) * 4) * 4;

    // ---- stage Q (once) ----
    {
        int row = tid >> 1, off = (tid & 1) * 16;
        const uint4* sH = (const uint4*)(Qhg + (row0 + t0 + row) * 128 + h * 32 + off);
        const uint4* sL = (const uint4*)(Qlg + (row0 + t0 + row) * 128 + h * 32 + off);
        uint4* dH = (uint4*)(QhS + row * SQ + off);
        uint4* dL = (uint4*)(QlS + row * SQ + off);
#pragma unroll
        for (int i = 0; i < 4; i++) { dH[i] = sH[i]; dL[i] = sL[i]; }
    }

    const int fr = lane >> 2, fc = lane & 3;
    const int qr = warp * 16 + fr;

    const unsigned aQh = sb + (warp * 16 * SQ) * 4 + laneoff;
    const unsigned aQl = aQh + 128 * SQ * 4;

    const int srow = tid >> 2, soff = (tid & 3) * 8;
    auto issue_stage = [&](int st, int kb) {
        size_t kg = (row0 + (size_t)kb * 64 + srow) * 128 + h * 32 + soff;
        unsigned base = sb + (9216 + st * 9216 + srow * SQ + soff) * 4;
        cpasync16(base,                 Khg + kg);
        cpasync16(base + 16,            Khg + kg + 4);
        cpasync16(base + 2304 * 4,      Klg + kg);
        cpasync16(base + 2304 * 4 + 16, Klg + kg + 4);
        cpasync16(base + 4608 * 4,      Vhg + kg);
        cpasync16(base + 4608 * 4 + 16, Vhg + kg + 4);
        cpasync16(base + 6912 * 4,      Vlg + kg);
        cpasync16(base + 6912 * 4 + 16, Vlg + kg + 4);
    };

    float Ov[8][4] = {};
    float l0s = 0.f, l1s = 0.f;

    issue_stage(0, 0);
    asm volatile("cp.async.commit_group;");

    for (int kb = 0; kb < T_TOK / 64; kb++) {
        const int cur = kb & 1;
        if (kb + 1 < T_TOK / 64) {
            issue_stage(cur ^ 1, kb + 1);
            asm volatile("cp.async.commit_group;");
            asm volatile("cp.async.wait_group 1;");
        } else {
            asm volatile("cp.async.wait_group 0;");
        }
        __syncthreads();

        const unsigned bstg = sb + (9216 + cur * 9216) * 4 + laneoff;
        const unsigned aKh = bstg;
        const unsigned aKl = bstg + 2304 * 4;
        const unsigned aVh = bstg + 4608 * 4;
        const unsigned aVl = bstg + 6912 * 4;

        // ---- S = Q K^T : 16x64 per warp ----
        float S[8][4];
#pragma unroll
        for (int j = 0; j < 8; j++)
            S[j][0] = S[j][1] = S[j][2] = S[j][3] = 0.f;

#pragma unroll
        for (int kk = 0; kk < 4; kk++) {
            uint4 Ah, Al;
            ldsm4(Ah, aQh + kk * 32);
            ldsm4(Al, aQl + kk * 32);
#pragma unroll
            for (int jp = 0; jp < 4; jp++) {
                uint4 Bh, Bl;
                ldsm4(Bh, aKh + (jp * 16 * SQ) * 4 + kk * 32);
                ldsm4(Bl, aKl + (jp * 16 * SQ) * 4 + kk * 32);
                MMA4(S[2 * jp],     Ah, Bh.x, Bh.z);
                MMA4(S[2 * jp],     Ah, Bl.x, Bl.z);
                MMA4(S[2 * jp],     Al, Bh.x, Bh.z);
                MMA4(S[2 * jp + 1], Ah, Bh.y, Bh.w);
                MMA4(S[2 * jp + 1], Ah, Bl.y, Bl.w);
                MMA4(S[2 * jp + 1], Al, Bh.y, Bh.w);
            }
        }

        // ---- softmax (fixed max 0; ex2) + truncation P-split + PV ----
#pragma unroll
        for (int kk = 0; kk < 4; kk++) {
            const int j0 = 2 * kk, j1 = 2 * kk + 1;
            float p00 = fexp2(S[j0][0]), p01 = fexp2(S[j0][1]);
            float p02 = fexp2(S[j0][2]), p03 = fexp2(S[j0][3]);
            float p10 = fexp2(S[j1][0]), p11 = fexp2(S[j1][1]);
            float p12 = fexp2(S[j1][2]), p13 = fexp2(S[j1][3]);
            l0s += (p00 + p01) + (p10 + p11);
            l1s += (p02 + p03) + (p12 + p13);
            uint4 Ph, Pl;
            {
                unsigned u00 = __float_as_uint(p00), u01 = __float_as_uint(p01);
                unsigned u02 = __float_as_uint(p02), u03 = __float_as_uint(p03);
                unsigned u10 = __float_as_uint(p10), u11 = __float_as_uint(p11);
                unsigned u12 = __float_as_uint(p12), u13 = __float_as_uint(p13);
                Ph.x = prmt_hi(u00, u01);
                Ph.y = prmt_hi(u02, u03);
                Ph.z = prmt_hi(u10, u11);
                Ph.w = prmt_hi(u12, u13);
                float r00 = p00 - __uint_as_float(u00 & 0xFFFF0000u);
                float r01 = p01 - __uint_as_float(u01 & 0xFFFF0000u);
                float r02 = p02 - __uint_as_float(u02 & 0xFFFF0000u);
                float r03 = p03 - __uint_as_float(u03 & 0xFFFF0000u);
                float r10 = p10 - __uint_as_float(u10 & 0xFFFF0000u);
                float r11 = p11 - __uint_as_float(u11 & 0xFFFF0000u);
                float r12 = p12 - __uint_as_float(u12 & 0xFFFF0000u);
                float r13 = p13 - __uint_as_float(u13 & 0xFFFF0000u);
                Pl.x = prmt_hi(__float_as_uint(r00), __float_as_uint(r01));
                Pl.y = prmt_hi(__float_as_uint(r02), __float_as_uint(r03));
                Pl.z = prmt_hi(__float_as_uint(r10), __float_as_uint(r11));
                Pl.w = prmt_hi(__float_as_uint(r12), __float_as_uint(r13));
            }
#pragma unroll
            for (int jp = 0; jp < 4; jp++) {
                uint4 Bh, Bl;
                ldsm4t(Bh, aVh + (kk * 16 * SQ) * 4 + jp * 32);
                ldsm4t(Bl, aVl + (kk * 16 * SQ) * 4 + jp * 32);
                MMA4(Ov[2 * jp],     Ph, Bh.x, Bh.y);
                MMA4(Ov[2 * jp],     Ph, Bl.x, Bl.y);
                MMA4(Ov[2 * jp],     Pl, Bh.x, Bh.y);
                MMA4(Ov[2 * jp + 1], Ph, Bh.z, Bh.w);
                MMA4(Ov[2 * jp + 1], Ph, Bl.z, Bl.w);
                MMA4(Ov[2 * jp + 1], Pl, Bh.z, Bh.w);
            }
        }
        __syncthreads();
    }

    // ---- epilogue: reduce l over the quad, normalize, store ----
    l0s += __shfl_xor_sync(0xffffffffu, l0s, 1);
    l0s += __shfl_xor_sync(0xffffffffu, l0s, 2);
    l1s += __shfl_xor_sync(0xffffffffu, l1s, 1);
    l1s += __shfl_xor_sync(0xffffffffu, l1s, 2);
    float inv0 = 1.0f / l0s, inv1 = 1.0f / l1s;
    const size_t feat0 = (size_t)s * CIN + h * DH;
    const size_t r0g = (size_t)b * T_TOK + t0 + qr;
    const size_t r1g = r0g + 8;
#pragma unroll
    for (int j = 0; j < 8; j++) {
        size_t col = feat0 + j * 8 + fc * 2;
        *(float2*)(O + r0g * (4 * CIN) + col) = make_float2(Ov[j][0] * inv0, Ov[j][1] * inv0);
        *(float2*)(O + r1g * (4 * CIN) + col) = make_float2(Ov[j][2] * inv1, Ov[j][3] * inv1);
    }
}

// ---------------------------------------------------------------------------
extern "C" void kernel_launch(void* const* d_in, const int* in_sizes, int n_in,
                              void* d_out, int out_size)
{
    const float* x    = (const float*)d_in[0];
    const float* w1   = (const float*)d_in[1];
    const float* bn1g = (const float*)d_in[2];
    const float* bn1b = (const float*)d_in[3];
    const float* bn1m = (const float*)d_in[4];
    const float* bn1v = (const float*)d_in[5];
    const float* dww  = (const float*)d_in[6];
    const float* pww  = (const float*)d_in[7];
    const float* bn2g = (const float*)d_in[8];
    const float* bn2b = (const float*)d_in[9];
    const float* bn2m = (const float*)d_in[10];
    const float* bn2v = (const float*)d_in[11];
    const float* Wq   = (const float*)d_in[12];
    const float* Wk   = (const float*)d_in[13];
    const float* Wv   = (const float*)d_in[14];
    const float* Wout = (const float*)d_in[15];
    float* out = (float*)d_out;

    void* p;
    cudaGetSymbolAddress(&p, g_identity); float* ident = (float*)p;
    cudaGetSymbolAddress(&p, g_R);        float* Rp    = (float*)p;
    cudaGetSymbolAddress(&p, g_O);        float* Op    = (float*)p;
    cudaGetSymbolAddress(&p, g_Qh);  unsigned* Qh = (unsigned*)p;
    cudaGetSymbolAddress(&p, g_Ql);  unsigned* Ql = (unsigned*)p;
    cudaGetSymbolAddress(&p, g_Kh);  unsigned* Kh = (unsigned*)p;
    cudaGetSymbolAddress(&p, g_Kl);  unsigned* Kl = (unsigned*)p;
    cudaGetSymbolAddress(&p, g_Vh);  unsigned* Vh = (unsigned*)p;
    cudaGetSymbolAddress(&p, g_Vl);  unsigned* Vl = (unsigned*)p;

    cudaFuncSetAttribute(gemm_mma, cudaFuncAttributeMaxDynamicSharedMemorySize, GEMM_SMEM);
    cudaFuncSetAttribute(gemm_qkv, cudaFuncAttributeMaxDynamicSharedMemorySize, GEMM_SMEM);
    cudaFuncSetAttribute(attn5, cudaFuncAttributeMaxDynamicSharedMemorySize, AT_SMEM);

    // [0] conv_in + BN1 (inline) -> identity ; channels [0,64) also into R[0]
    gemm_mma<<<dim3(4, 36), 256, GEMM_SMEM>>>(
        x, w1, NB * T_TOK, CIN, CIN, ident, bn1g, bn1b, bn1m, bn1v, Rp, C4);

    // [1..3] Res2Net scales (fused dw+pw+BN2, 8-token blocks, grid 576)
    for (int s = 1; s <= 3; s++) {
        const float* prev = (s == 1) ? nullptr : (Rp + (size_t)(s - 1) * NB * T_TOK * C4);
        dwpw8<<<(NB * T_TOK) / 8, 256>>>(
            ident, prev, dww, pww, bn2g, bn2b, bn2m, bn2v,
            Rp + (size_t)s * NB * T_TOK * C4, s);
    }

    // [4] fused Q/K/V projections -> pre-split hi/lo (Q scaled by log2e)
    gemm_qkv<<<dim3(4, 144, 3), 256, GEMM_SMEM>>>(
        Rp, Wq, Wk, Wv, Qh, Ql, Kh, Kl, Vh, Vl);

    // [5] flash attention
    attn5<<<dim3(T_TOK / 128, NS * NB * NH), 256, AT_SMEM>>>(
        Qh, Ql, Kh, Kl, Vh, Vl, Op);

    // [6] output projection -> d_out
    gemm_mma<<<dim3(4, 36), 256, GEMM_SMEM>>>(
        Op, Wout, NB * T_TOK, CIN, 4 * CIN, out,
        nullptr, nullptr, nullptr, nullptr, nullptr, 0);
}

// round 14
// speedup vs baseline: 1.4631x; 1.2168x over previous
#include <cuda_runtime.h>
#include <cuda_bf16.h>
#include <cuda_fp16.h>

// Problem constants (fixed shapes)
#define T_TOK 2304
#define NB    2
#define CIN   256
#define C4    64
#define NS    4
#define NH    4
#define DH    64
#define HH    48
#define WW    48

// ---------------- scratch (device globals; no allocation allowed) ----------
__device__ __align__(128) float g_identity[NB * T_TOK * CIN];
__device__ __align__(128) float g_R[NS * NB * T_TOK * C4];
__device__ __align__(128) float g_O[NB * T_TOK * 4 * CIN];
#define NPAIR (NS * NB * T_TOK * (CIN / 2))
__device__ __align__(128) unsigned g_Qh[NPAIR], g_Ql[NPAIR];
__device__ __align__(128) unsigned g_Kh[NPAIR], g_Kl[NPAIR];
__device__ __align__(128) unsigned g_Vh[NPAIR], g_Vl[NPAIR];

// =================== split helpers ==================================
// bf16 (dense GEMMs, 3-term split)
__device__ __forceinline__ unsigned pack2(float x, float y) {
    __nv_bfloat162 t = __floats2bfloat162_rn(x, y);
    return reinterpret_cast<unsigned&>(t);
}
__device__ __forceinline__ void split_pair(float x, float y, unsigned& h, unsigned& l) {
    float hx = __bfloat162float(__float2bfloat16_rn(x));
    float hy = __bfloat162float(__float2bfloat16_rn(y));
    h = pack2(hx, hy);
    l = pack2(x - hx, y - hy);
}
// fp16 (attention Q/K/V, 2-term split)
__device__ __forceinline__ unsigned pack2h(float x, float y) {
    __half2 t = __floats2half2_rn(x, y);
    return reinterpret_cast<unsigned&>(t);
}
__device__ __forceinline__ void split_pair_h(float x, float y, unsigned& h, unsigned& l) {
    float hx = __half2float(__float2half_rn(x));
    float hy = __half2float(__float2half_rn(y));
    h = pack2h(hx, hy);
    l = pack2h(x - hx, y - hy);
}
__device__ __forceinline__ void ldsm4(uint4& r, unsigned addr) {
    asm volatile("ldmatrix.sync.aligned.m8n8.x4.shared.b16 {%0,%1,%2,%3}, [%4];"
                 : "=r"(r.x), "=r"(r.y), "=r"(r.z), "=r"(r.w) : "r"(addr));
}
__device__ __forceinline__ void ldsm4t(uint4& r, unsigned addr) {
    asm volatile("ldmatrix.sync.aligned.m8n8.x4.trans.shared.b16 {%0,%1,%2,%3}, [%4];"
                 : "=r"(r.x), "=r"(r.y), "=r"(r.z), "=r"(r.w) : "r"(addr));
}
__device__ __forceinline__ void cpasync16(unsigned dst, const void* src) {
    asm volatile("cp.async.cg.shared.global [%0], [%1], 16;" :: "r"(dst), "l"(src));
}
__device__ __forceinline__ unsigned smem_u32(const void* p) {
    return (unsigned)__cvta_generic_to_shared(p);
}
__device__ __forceinline__ float fexp2(float x) {
    float y;
    asm("ex2.approx.f32 %0, %1;" : "=f"(y) : "f"(x));
    return y;
}

#define MMA4(C, A, B0, B1)                                                    \
    asm volatile("mma.sync.aligned.m16n8k16.row.col.f32.bf16.bf16.f32 "       \
                 "{%0,%1,%2,%3}, {%4,%5,%6,%7}, {%8,%9}, {%0,%1,%2,%3};"      \
                 : "+f"(C[0]), "+f"(C[1]), "+f"(C[2]), "+f"(C[3])             \
                 : "r"(A.x), "r"(A.y), "r"(A.z), "r"(A.w), "r"(B0), "r"(B1))

#define MMA4H(C, A, B0, B1)                                                   \
    asm volatile("mma.sync.aligned.m16n8k16.row.col.f32.f16.f16.f32 "         \
                 "{%0,%1,%2,%3}, {%4,%5,%6,%7}, {%8,%9}, {%0,%1,%2,%3};"      \
                 : "+f"(C[0]), "+f"(C[1]), "+f"(C[2]), "+f"(C[3])             \
                 : "r"(A.x), "r"(A.y), "r"(A.z), "r"(A.w), "r"(B0), "r"(B1))

#define SQ 36

// ============ tensor-core split GEMM: C[M,N] = A[M,K] @ W[N,K]^T ===========
// BN (eval) folded inline from raw g/b/m/v when bng != nullptr.
#define GEMM_SMEM (384 * SQ * 4)
__global__ void __launch_bounds__(256) gemm_mma(
    const float* __restrict__ A, const float* __restrict__ W,
    int M, int N, int K,
    float* __restrict__ Cf,
    const float* __restrict__ bng, const float* __restrict__ bnb,
    const float* __restrict__ bnm, const float* __restrict__ bnv,
    float* __restrict__ C2, int c2cols)
{
    extern __shared__ unsigned gsm[];
    unsigned* AhS = gsm;
    unsigned* AlS = gsm + 128 * SQ;
    unsigned* WhS = gsm + 256 * SQ;
    unsigned* WlS = gsm + 320 * SQ;

    const int tid = threadIdx.x, lane = tid & 31, warp = tid >> 5;
    const int m0 = blockIdx.y * 128, n0 = blockIdx.x * 64;

    const unsigned sb = smem_u32(gsm);
    const unsigned laneoff =
        (((lane & 7) + ((lane >> 3) & 1) * 8) * SQ + (lane >> 4) * 4) * 4;
    const unsigned aA = sb + (warp * 16 * SQ) * 4 + laneoff;
    const unsigned aAl = aA + 128 * SQ * 4;
    const unsigned aW = sb + (256 * SQ) * 4 + laneoff;
    const unsigned aWl = aW + 64 * SQ * 4;

    float S[8][4] = {};

    for (int k0 = 0; k0 < K; k0 += 64) {
        __syncthreads();
        {
            int row = tid >> 1, half = tid & 1;
            const float* src = A + (size_t)(m0 + row) * K + k0 + half * 32;
            unsigned* dh = AhS + row * SQ + half * 16;
            unsigned* dl = AlS + row * SQ + half * 16;
#pragma unroll
            for (int i = 0; i < 8; i++) {
                float4 v = *(const float4*)(src + i * 4);
                split_pair(v.x, v.y, dh[i * 2], dl[i * 2]);
                split_pair(v.z, v.w, dh[i * 2 + 1], dl[i * 2 + 1]);
            }
        }
        {
            int row = tid >> 2, q = tid & 3;
            const float* src = W + (size_t)(n0 + row) * K + k0 + q * 16;
            unsigned* dh = WhS + row * SQ + q * 8;
            unsigned* dl = WlS + row * SQ + q * 8;
#pragma unroll
            for (int i = 0; i < 4; i++) {
                float4 v = *(const float4*)(src + i * 4);
                split_pair(v.x, v.y, dh[i * 2], dl[i * 2]);
                split_pair(v.z, v.w, dh[i * 2 + 1], dl[i * 2 + 1]);
            }
        }
        __syncthreads();

#pragma unroll
        for (int kk = 0; kk < 4; kk++) {
            uint4 Ah, Al;
            ldsm4(Ah, aA + kk * 32);
            ldsm4(Al, aAl + kk * 32);
#pragma unroll
            for (int jp = 0; jp < 4; jp++) {
                uint4 Bh, Bl;
                ldsm4(Bh, aW + (jp * 16 * SQ) * 4 + kk * 32);
                ldsm4(Bl, aWl + (jp * 16 * SQ) * 4 + kk * 32);
                MMA4(S[2 * jp],     Ah, Bh.x, Bh.z);
                MMA4(S[2 * jp],     Ah, Bl.x, Bl.z);
                MMA4(S[2 * jp],     Al, Bh.x, Bh.z);
                MMA4(S[2 * jp + 1], Ah, Bh.y, Bh.w);
                MMA4(S[2 * jp + 1], Ah, Bl.y, Bl.w);
                MMA4(S[2 * jp + 1], Al, Bh.y, Bh.w);
            }
        }
    }

    const int fr = lane >> 2, fc = lane & 3;
    const int r0 = m0 + warp * 16 + fr;
    const int r1 = r0 + 8;
#pragma unroll
    for (int j = 0; j < 8; j++) {
        int col = n0 + j * 8 + fc * 2;
        float v0 = S[j][0], v1 = S[j][1], v2 = S[j][2], v3 = S[j][3];
        if (bng) {
            float s0 = bng[col] * rsqrtf(bnv[col] + 1e-5f);
            float s1 = bng[col + 1] * rsqrtf(bnv[col + 1] + 1e-5f);
            float b0 = bnb[col] - bnm[col] * s0;
            float b1 = bnb[col + 1] - bnm[col + 1] * s1;
            v0 = v0 * s0 + b0; v1 = v1 * s1 + b1;
            v2 = v2 * s0 + b0; v3 = v3 * s1 + b1;
        }
        *(float2*)(Cf + (size_t)r0 * N + col) = make_float2(v0, v1);
        *(float2*)(Cf + (size_t)r1 * N + col) = make_float2(v2, v3);
        if (C2 && col < c2cols) {
            *(float2*)(C2 + (size_t)r0 * c2cols + col) = make_float2(v0, v1);
            *(float2*)(C2 + (size_t)r1 * c2cols + col) = make_float2(v2, v3);
        }
    }
}

// ============ fused QKV projection (single launch, grid.z selects) =========
// Epilogue writes fp16 hi/lo pairs (2-term attention split).
__global__ void __launch_bounds__(256) gemm_qkv(
    const float* __restrict__ A,
    const float* __restrict__ Wq, const float* __restrict__ Wk, const float* __restrict__ Wv,
    unsigned* __restrict__ Qh, unsigned* __restrict__ Ql,
    unsigned* __restrict__ Kh, unsigned* __restrict__ Kl,
    unsigned* __restrict__ Vh, unsigned* __restrict__ Vl)
{
    extern __shared__ unsigned gsm[];
    unsigned* AhS = gsm;
    unsigned* AlS = gsm + 128 * SQ;
    unsigned* WhS = gsm + 256 * SQ;
    unsigned* WlS = gsm + 320 * SQ;

    const int tid = threadIdx.x, lane = tid & 31, warp = tid >> 5;
    const int m0 = blockIdx.y * 128, n0 = blockIdx.x * 64;
    const int z = blockIdx.z;
    const float* W = (z == 0) ? Wq : (z == 1) ? Wk : Wv;
    unsigned* Chi = (z == 0) ? Qh : (z == 1) ? Kh : Vh;
    unsigned* Clo = (z == 0) ? Ql : (z == 1) ? Kl : Vl;
    const float mult = (z == 0) ? 1.4426950408889634f : 1.0f;
    const int K = C4, N = CIN;

    const unsigned sb = smem_u32(gsm);
    const unsigned laneoff =
        (((lane & 7) + ((lane >> 3) & 1) * 8) * SQ + (lane >> 4) * 4) * 4;
    const unsigned aA = sb + (warp * 16 * SQ) * 4 + laneoff;
    const unsigned aAl = aA + 128 * SQ * 4;
    const unsigned aW = sb + (256 * SQ) * 4 + laneoff;
    const unsigned aWl = aW + 64 * SQ * 4;

    float S[8][4] = {};

    {
        int row = tid >> 1, half = tid & 1;
        const float* src = A + (size_t)(m0 + row) * K + half * 32;
        unsigned* dh = AhS + row * SQ + half * 16;
        unsigned* dl = AlS + row * SQ + half * 16;
#pragma unroll
        for (int i = 0; i < 8; i++) {
            float4 v = *(const float4*)(src + i * 4);
            split_pair(v.x, v.y, dh[i * 2], dl[i * 2]);
            split_pair(v.z, v.w, dh[i * 2 + 1], dl[i * 2 + 1]);
        }
    }
    {
        int row = tid >> 2, q = tid & 3;
        const float* src = W + (size_t)(n0 + row) * K + q * 16;
        unsigned* dh = WhS + row * SQ + q * 8;
        unsigned* dl = WlS + row * SQ + q * 8;
#pragma unroll
        for (int i = 0; i < 4; i++) {
            float4 v = *(const float4*)(src + i * 4);
            split_pair(v.x, v.y, dh[i * 2], dl[i * 2]);
            split_pair(v.z, v.w, dh[i * 2 + 1], dl[i * 2 + 1]);
        }
    }
    __syncthreads();

#pragma unroll
    for (int kk = 0; kk < 4; kk++) {
        uint4 Ah, Al;
        ldsm4(Ah, aA + kk * 32);
        ldsm4(Al, aAl + kk * 32);
#pragma unroll
        for (int jp = 0; jp < 4; jp++) {
            uint4 Bh, Bl;
            ldsm4(Bh, aW + (jp * 16 * SQ) * 4 + kk * 32);
            ldsm4(Bl, aWl + (jp * 16 * SQ) * 4 + kk * 32);
            MMA4(S[2 * jp],     Ah, Bh.x, Bh.z);
            MMA4(S[2 * jp],     Ah, Bl.x, Bl.z);
            MMA4(S[2 * jp],     Al, Bh.x, Bh.z);
            MMA4(S[2 * jp + 1], Ah, Bh.y, Bh.w);
            MMA4(S[2 * jp + 1], Ah, Bl.y, Bl.w);
            MMA4(S[2 * jp + 1], Al, Bh.y, Bh.w);
        }
    }

    const int fr = lane >> 2, fc = lane & 3;
    const int r0 = m0 + warp * 16 + fr;
    const int r1 = r0 + 8;
#pragma unroll
    for (int j = 0; j < 8; j++) {
        int col = n0 + j * 8 + fc * 2;
        float v0 = S[j][0] * mult, v1 = S[j][1] * mult;
        float v2 = S[j][2] * mult, v3 = S[j][3] * mult;
        unsigned h0, l0, h1, l1;
        split_pair_h(v0, v1, h0, l0);
        split_pair_h(v2, v3, h1, l1);
        int ci = col >> 1, nw = N >> 1;
        Chi[(size_t)r0 * nw + ci] = h0; Clo[(size_t)r0 * nw + ci] = l0;
        Chi[(size_t)r1 * nw + ci] = h1; Clo[(size_t)r1 * nw + ci] = l1;
    }
}

// ============ fused depthwise 3x3 + pointwise 1x1 + BN2 (8-token blocks) ===
__global__ void __launch_bounds__(256) dwpw8(
    const float* __restrict__ ident, const float* __restrict__ Rprev,
    const float* __restrict__ dw, const float* __restrict__ pw,
    const float* __restrict__ bn2g, const float* __restrict__ bn2b,
    const float* __restrict__ bn2m, const float* __restrict__ bn2v,
    float* __restrict__ Rout, int s)
{
    __shared__ float Ws[64 * 65];
    __shared__ float Ds[8 * 68];
    __shared__ float wsm[C4 * 9];
    const int tid = threadIdx.x;

#pragma unroll
    for (int k = 0; k < 16; k++) {
        int idx = tid + k * 256;
        int oo = idx >> 6, cc = idx & 63;
        Ws[cc * 65 + oo] = pw[idx];
    }
    for (int i = tid; i < C4 * 9; i += 256) wsm[i] = dw[i];
    __syncthreads();

    const int lt = tid >> 5;
    const int ol = tid & 31;
    const int g = blockIdx.x * 8 + lt;
    const int b = g / T_TOK, t = g - b * T_TOK;
    const int hh = t / WW, ww = t % WW;

    {
        const float* ib = ident + (size_t)b * T_TOK * CIN + s * C4;
        const float* rb = Rprev ? (Rprev + (size_t)b * T_TOK * C4) : nullptr;
        float a0 = 0.f, a1 = 0.f;
        const int c0 = ol, c1 = ol + 32;
#pragma unroll
        for (int kh = 0; kh < 3; kh++) {
            int h2 = hh + kh - 1;
            if ((unsigned)h2 >= HH) continue;
#pragma unroll
            for (int kw = 0; kw < 3; kw++) {
                int w2 = ww + kw - 1;
                if ((unsigned)w2 >= WW) continue;
                int tt = h2 * WW + w2;
                float v0 = ib[(size_t)tt * CIN + c0];
                float v1 = ib[(size_t)tt * CIN + c1];
                if (rb) {
                    v0 += rb[(size_t)tt * C4 + c0];
                    v1 += rb[(size_t)tt * C4 + c1];
                }
                a0 += v0 * wsm[c0 * 9 + kh * 3 + kw];
                a1 += v1 * wsm[c1 * 9 + kh * 3 + kw];
            }
        }
        Ds[lt * 68 + c0] = a0;
        Ds[lt * 68 + c1] = a1;
    }
    __syncthreads();

    float acc0 = 0.f, acc1 = 0.f;
#pragma unroll 16
    for (int c = 0; c < 64; c++) {
        float d = Ds[lt * 68 + c];
        acc0 += d * Ws[c * 65 + ol];
        acc1 += d * Ws[c * 65 + ol + 32];
    }
    {
        float sc0 = bn2g[ol] * rsqrtf(bn2v[ol] + 1e-5f);
        float bi0 = bn2b[ol] - bn2m[ol] * sc0;
        float sc1 = bn2g[ol + 32] * rsqrtf(bn2v[ol + 32] + 1e-5f);
        float bi1 = bn2b[ol + 32] - bn2m[ol + 32] * sc1;
        Rout[(size_t)g * C4 + ol]      = acc0 * sc0 + bi0;
        Rout[(size_t)g * C4 + ol + 32] = acc1 * sc1 + bi1;
    }
}

// ================= fp16 tensor-core flash attention ========================
// 8 warps, Q-tile 128, K-tile 64; cp.async double-buffered K/V.
// fp16 2-term split: S = Qh*(Kh+Kl), O = Ph*(Vh+Vl). No Ql/Pl.
// Fixed-max softmax (Q pre-scaled by log2e -> ex2); V via ldmatrix.trans.
// smem u32: Qh[0..4608), stage st at 4608+st*9216: Kh+0,Kl+2304,Vh+4608,Vl+6912
#define AT_SMEM (23040 * 4)    // 92160 B -> 2 CTAs/SM
__global__ void __launch_bounds__(256, 2) attn6(
    const unsigned* __restrict__ Qhg,
    const unsigned* __restrict__ Khg, const unsigned* __restrict__ Klg,
    const unsigned* __restrict__ Vhg, const unsigned* __restrict__ Vlg,
    float* __restrict__ O)
{
    extern __shared__ unsigned smu[];
    unsigned* QhS = smu;

    const int tid = threadIdx.x, lane = tid & 31, warp = tid >> 5;
    const int y = blockIdx.y;
    const int s = y >> 3, b = (y >> 2) & 1, h = y & 3;
    const int t0 = blockIdx.x * 128;
    const size_t row0 = (size_t)(s * NB + b) * T_TOK;

    const unsigned sb = smem_u32(smu);
    const unsigned laneoff =
        (((lane & 7) + ((lane >> 3) & 1) * 8) * SQ + (lane >> 4) * 4) * 4;

    // ---- stage Q hi (once) ----
    {
        int row = tid >> 1, off = (tid & 1) * 16;
        const uint4* sH = (const uint4*)(Qhg + (row0 + t0 + row) * 128 + h * 32 + off);
        uint4* dH = (uint4*)(QhS + row * SQ + off);
#pragma unroll
        for (int i = 0; i < 4; i++) dH[i] = sH[i];
    }

    const int fr = lane >> 2, fc = lane & 3;
    const int qr = warp * 16 + fr;

    const unsigned aQh = sb + (warp * 16 * SQ) * 4 + laneoff;

    const int srow = tid >> 2, soff = (tid & 3) * 8;
    auto issue_stage = [&](int st, int kb) {
        size_t kg = (row0 + (size_t)kb * 64 + srow) * 128 + h * 32 + soff;
        unsigned base = sb + (4608 + st * 9216 + srow * SQ + soff) * 4;
        cpasync16(base,                 Khg + kg);
        cpasync16(base + 16,            Khg + kg + 4);
        cpasync16(base + 2304 * 4,      Klg + kg);
        cpasync16(base + 2304 * 4 + 16, Klg + kg + 4);
        cpasync16(base + 4608 * 4,      Vhg + kg);
        cpasync16(base + 4608 * 4 + 16, Vhg + kg + 4);
        cpasync16(base + 6912 * 4,      Vlg + kg);
        cpasync16(base + 6912 * 4 + 16, Vlg + kg + 4);
    };

    float Ov[8][4] = {};
    float l0s = 0.f, l1s = 0.f;

    issue_stage(0, 0);
    asm volatile("cp.async.commit_group;");

    for (int kb = 0; kb < T_TOK / 64; kb++) {
        const int cur = kb & 1;
        if (kb + 1 < T_TOK / 64) {
            issue_stage(cur ^ 1, kb + 1);
            asm volatile("cp.async.commit_group;");
            asm volatile("cp.async.wait_group 1;");
        } else {
            asm volatile("cp.async.wait_group 0;");
        }
        __syncthreads();

        const unsigned bstg = sb + (4608 + cur * 9216) * 4 + laneoff;
        const unsigned aKh = bstg;
        const unsigned aKl = bstg + 2304 * 4;
        const unsigned aVh = bstg + 4608 * 4;
        const unsigned aVl = bstg + 6912 * 4;

        // ---- S = Qh (Kh + Kl)^T : 16x64 per warp, 2 terms ----
        float S[8][4];
#pragma unroll
        for (int j = 0; j < 8; j++)
            S[j][0] = S[j][1] = S[j][2] = S[j][3] = 0.f;

#pragma unroll
        for (int kk = 0; kk < 4; kk++) {
            uint4 Ah;
            ldsm4(Ah, aQh + kk * 32);
#pragma unroll
            for (int jp = 0; jp < 4; jp++) {
                uint4 Bh, Bl;
                ldsm4(Bh, aKh + (jp * 16 * SQ) * 4 + kk * 32);
                ldsm4(Bl, aKl + (jp * 16 * SQ) * 4 + kk * 32);
                MMA4H(S[2 * jp],     Ah, Bh.x, Bh.z);
                MMA4H(S[2 * jp],     Ah, Bl.x, Bl.z);
                MMA4H(S[2 * jp + 1], Ah, Bh.y, Bh.w);
                MMA4H(S[2 * jp + 1], Ah, Bl.y, Bl.w);
            }
        }

        // ---- softmax (fixed max 0; ex2) + fp16 P + PV (2 terms) ----
#pragma unroll
        for (int kk = 0; kk < 4; kk++) {
            const int j0 = 2 * kk, j1 = 2 * kk + 1;
            float p00 = fexp2(S[j0][0]), p01 = fexp2(S[j0][1]);
            float p02 = fexp2(S[j0][2]), p03 = fexp2(S[j0][3]);
            float p10 = fexp2(S[j1][0]), p11 = fexp2(S[j1][1]);
            float p12 = fexp2(S[j1][2]), p13 = fexp2(S[j1][3]);
            l0s += (p00 + p01) + (p10 + p11);
            l1s += (p02 + p03) + (p12 + p13);
            uint4 Ph;
            Ph.x = pack2h(p00, p01);
            Ph.y = pack2h(p02, p03);
            Ph.z = pack2h(p10, p11);
            Ph.w = pack2h(p12, p13);
#pragma unroll
            for (int jp = 0; jp < 4; jp++) {
                uint4 Bh, Bl;
                ldsm4t(Bh, aVh + (kk * 16 * SQ) * 4 + jp * 32);
                ldsm4t(Bl, aVl + (kk * 16 * SQ) * 4 + jp * 32);
                MMA4H(Ov[2 * jp],     Ph, Bh.x, Bh.y);
                MMA4H(Ov[2 * jp],     Ph, Bl.x, Bl.y);
                MMA4H(Ov[2 * jp + 1], Ph, Bh.z, Bh.w);
                MMA4H(Ov[2 * jp + 1], Ph, Bl.z, Bl.w);
            }
        }
        __syncthreads();
    }

    // ---- epilogue: reduce l over the quad, normalize, store ----
    l0s += __shfl_xor_sync(0xffffffffu, l0s, 1);
    l0s += __shfl_xor_sync(0xffffffffu, l0s, 2);
    l1s += __shfl_xor_sync(0xffffffffu, l1s, 1);
    l1s += __shfl_xor_sync(0xffffffffu, l1s, 2);
    float inv0 = 1.0f / l0s, inv1 = 1.0f / l1s;
    const size_t feat0 = (size_t)s * CIN + h * DH;
    const size_t r0g = (size_t)b * T_TOK + t0 + qr;
    const size_t r1g = r0g + 8;
#pragma unroll
    for (int j = 0; j < 8; j++) {
        size_t col = feat0 + j * 8 + fc * 2;
        *(float2*)(O + r0g * (4 * CIN) + col) = make_float2(Ov[j][0] * inv0, Ov[j][1] * inv0);
        *(float2*)(O + r1g * (4 * CIN) + col) = make_float2(Ov[j][2] * inv1, Ov[j][3] * inv1);
    }
}

// ---------------------------------------------------------------------------
extern "C" void kernel_launch(void* const* d_in, const int* in_sizes, int n_in,
                              void* d_out, int out_size)
{
    const float* x    = (const float*)d_in[0];
    const float* w1   = (const float*)d_in[1];
    const float* bn1g = (const float*)d_in[2];
    const float* bn1b = (const float*)d_in[3];
    const float* bn1m = (const float*)d_in[4];
    const float* bn1v = (const float*)d_in[5];
    const float* dww  = (const float*)d_in[6];
    const float* pww  = (const float*)d_in[7];
    const float* bn2g = (const float*)d_in[8];
    const float* bn2b = (const float*)d_in[9];
    const float* bn2m = (const float*)d_in[10];
    const float* bn2v = (const float*)d_in[11];
    const float* Wq   = (const float*)d_in[12];
    const float* Wk   = (const float*)d_in[13];
    const float* Wv   = (const float*)d_in[14];
    const float* Wout = (const float*)d_in[15];
    float* out = (float*)d_out;

    void* p;
    cudaGetSymbolAddress(&p, g_identity); float* ident = (float*)p;
    cudaGetSymbolAddress(&p, g_R);        float* Rp    = (float*)p;
    cudaGetSymbolAddress(&p, g_O);        float* Op    = (float*)p;
    cudaGetSymbolAddress(&p, g_Qh);  unsigned* Qh = (unsigned*)p;
    cudaGetSymbolAddress(&p, g_Ql);  unsigned* Ql = (unsigned*)p;
    cudaGetSymbolAddress(&p, g_Kh);  unsigned* Kh = (unsigned*)p;
    cudaGetSymbolAddress(&p, g_Kl);  unsigned* Kl = (unsigned*)p;
    cudaGetSymbolAddress(&p, g_Vh);  unsigned* Vh = (unsigned*)p;
    cudaGetSymbolAddress(&p, g_Vl);  unsigned* Vl = (unsigned*)p;

    cudaFuncSetAttribute(gemm_mma, cudaFuncAttributeMaxDynamicSharedMemorySize, GEMM_SMEM);
    cudaFuncSetAttribute(gemm_qkv, cudaFuncAttributeMaxDynamicSharedMemorySize, GEMM_SMEM);
    cudaFuncSetAttribute(attn6, cudaFuncAttributeMaxDynamicSharedMemorySize, AT_SMEM);

    // [0] conv_in + BN1 (inline) -> identity ; channels [0,64) also into R[0]
    gemm_mma<<<dim3(4, 36), 256, GEMM_SMEM>>>(
        x, w1, NB * T_TOK, CIN, CIN, ident, bn1g, bn1b, bn1m, bn1v, Rp, C4);

    // [1..3] Res2Net scales (fused dw+pw+BN2, 8-token blocks, grid 576)
    for (int s = 1; s <= 3; s++) {
        const float* prev = (s == 1) ? nullptr : (Rp + (size_t)(s - 1) * NB * T_TOK * C4);
        dwpw8<<<(NB * T_TOK) / 8, 256>>>(
            ident, prev, dww, pww, bn2g, bn2b, bn2m, bn2v,
            Rp + (size_t)s * NB * T_TOK * C4, s);
    }

    // [4] fused Q/K/V projections -> fp16 hi/lo (Q scaled by log2e)
    gemm_qkv<<<dim3(4, 144, 3), 256, GEMM_SMEM>>>(
        Rp, Wq, Wk, Wv, Qh, Ql, Kh, Kl, Vh, Vl);

    // [5] fp16 flash attention (2+2 split terms)
    attn6<<<dim3(T_TOK / 128, NS * NB * NH), 256, AT_SMEM>>>(
        Qh, Kh, Kl, Vh, Vl, Op);

    // [6] output projection -> d_out
    gemm_mma<<<dim3(4, 36), 256, GEMM_SMEM>>>(
        Op, Wout, NB * T_TOK, CIN, 4 * CIN, out,
        nullptr, nullptr, nullptr, nullptr, nullptr, 0);
}

// round 15
// speedup vs baseline: 2.2099x; 1.5104x over previous
#include <cuda_runtime.h>
#include <cuda_bf16.h>
#include <cuda_fp16.h>

// Problem constants (fixed shapes)
#define T_TOK 2304
#define NB    2
#define CIN   256
#define C4    64
#define NS    4
#define NH    4
#define DH    64
#define HH    48
#define WW    48

// ---------------- scratch (device globals; no allocation allowed) ----------
__device__ __align__(128) float g_identity[NB * T_TOK * CIN];
__device__ __align__(128) float g_R[NS * NB * T_TOK * C4];
__device__ __align__(128) float g_O[NB * T_TOK * 4 * CIN];
#define NPAIR (NS * NB * T_TOK * (CIN / 2))
__device__ __align__(128) unsigned g_Qh[NPAIR];
__device__ __align__(128) unsigned g_Kh[NPAIR];
__device__ __align__(128) unsigned g_Vh[NPAIR];

// =================== split helpers ==================================
// bf16 (dense GEMMs, 3-term split)
__device__ __forceinline__ unsigned pack2(float x, float y) {
    __nv_bfloat162 t = __floats2bfloat162_rn(x, y);
    return reinterpret_cast<unsigned&>(t);
}
__device__ __forceinline__ void split_pair(float x, float y, unsigned& h, unsigned& l) {
    float hx = __bfloat162float(__float2bfloat16_rn(x));
    float hy = __bfloat162float(__float2bfloat16_rn(y));
    h = pack2(hx, hy);
    l = pack2(x - hx, y - hy);
}
// fp16 (attention, plain rounding)
__device__ __forceinline__ unsigned pack2h(float x, float y) {
    __half2 t = __floats2half2_rn(x, y);
    return reinterpret_cast<unsigned&>(t);
}
__device__ __forceinline__ void ldsm4(uint4& r, unsigned addr) {
    asm volatile("ldmatrix.sync.aligned.m8n8.x4.shared.b16 {%0,%1,%2,%3}, [%4];"
                 : "=r"(r.x), "=r"(r.y), "=r"(r.z), "=r"(r.w) : "r"(addr));
}
__device__ __forceinline__ void ldsm4t(uint4& r, unsigned addr) {
    asm volatile("ldmatrix.sync.aligned.m8n8.x4.trans.shared.b16 {%0,%1,%2,%3}, [%4];"
                 : "=r"(r.x), "=r"(r.y), "=r"(r.z), "=r"(r.w) : "r"(addr));
}
__device__ __forceinline__ void cpasync16(unsigned dst, const void* src) {
    asm volatile("cp.async.cg.shared.global [%0], [%1], 16;" :: "r"(dst), "l"(src));
}
__device__ __forceinline__ unsigned smem_u32(const void* p) {
    return (unsigned)__cvta_generic_to_shared(p);
}
__device__ __forceinline__ float fexp2(float x) {
    float y;
    asm("ex2.approx.f32 %0, %1;" : "=f"(y) : "f"(x));
    return y;
}

#define MMA4(C, A, B0, B1)                                                    \
    asm volatile("mma.sync.aligned.m16n8k16.row.col.f32.bf16.bf16.f32 "       \
                 "{%0,%1,%2,%3}, {%4,%5,%6,%7}, {%8,%9}, {%0,%1,%2,%3};"      \
                 : "+f"(C[0]), "+f"(C[1]), "+f"(C[2]), "+f"(C[3])             \
                 : "r"(A.x), "r"(A.y), "r"(A.z), "r"(A.w), "r"(B0), "r"(B1))

#define MMA4H(C, A, B0, B1)                                                   \
    asm volatile("mma.sync.aligned.m16n8k16.row.col.f32.f16.f16.f32 "         \
                 "{%0,%1,%2,%3}, {%4,%5,%6,%7}, {%8,%9}, {%0,%1,%2,%3};"      \
                 : "+f"(C[0]), "+f"(C[1]), "+f"(C[2]), "+f"(C[3])             \
                 : "r"(A.x), "r"(A.y), "r"(A.z), "r"(A.w), "r"(B0), "r"(B1))

#define SQ 36

// ============ tensor-core split GEMM: C[M,N] = A[M,K] @ W[N,K]^T ===========
// BN (eval) folded inline from raw g/b/m/v when bng != nullptr.
#define GEMM_SMEM (384 * SQ * 4)
__global__ void __launch_bounds__(256) gemm_mma(
    const float* __restrict__ A, const float* __restrict__ W,
    int M, int N, int K,
    float* __restrict__ Cf,
    const float* __restrict__ bng, const float* __restrict__ bnb,
    const float* __restrict__ bnm, const float* __restrict__ bnv,
    float* __restrict__ C2, int c2cols)
{
    extern __shared__ unsigned gsm[];
    unsigned* AhS = gsm;
    unsigned* AlS = gsm + 128 * SQ;
    unsigned* WhS = gsm + 256 * SQ;
    unsigned* WlS = gsm + 320 * SQ;

    const int tid = threadIdx.x, lane = tid & 31, warp = tid >> 5;
    const int m0 = blockIdx.y * 128, n0 = blockIdx.x * 64;

    const unsigned sb = smem_u32(gsm);
    const unsigned laneoff =
        (((lane & 7) + ((lane >> 3) & 1) * 8) * SQ + (lane >> 4) * 4) * 4;
    const unsigned aA = sb + (warp * 16 * SQ) * 4 + laneoff;
    const unsigned aAl = aA + 128 * SQ * 4;
    const unsigned aW = sb + (256 * SQ) * 4 + laneoff;
    const unsigned aWl = aW + 64 * SQ * 4;

    float S[8][4] = {};

    for (int k0 = 0; k0 < K; k0 += 64) {
        __syncthreads();
        {
            int row = tid >> 1, half = tid & 1;
            const float* src = A + (size_t)(m0 + row) * K + k0 + half * 32;
            unsigned* dh = AhS + row * SQ + half * 16;
            unsigned* dl = AlS + row * SQ + half * 16;
#pragma unroll
            for (int i = 0; i < 8; i++) {
                float4 v = *(const float4*)(src + i * 4);
                split_pair(v.x, v.y, dh[i * 2], dl[i * 2]);
                split_pair(v.z, v.w, dh[i * 2 + 1], dl[i * 2 + 1]);
            }
        }
        {
            int row = tid >> 2, q = tid & 3;
            const float* src = W + (size_t)(n0 + row) * K + k0 + q * 16;
            unsigned* dh = WhS + row * SQ + q * 8;
            unsigned* dl = WlS + row * SQ + q * 8;
#pragma unroll
            for (int i = 0; i < 4; i++) {
                float4 v = *(const float4*)(src + i * 4);
                split_pair(v.x, v.y, dh[i * 2], dl[i * 2]);
                split_pair(v.z, v.w, dh[i * 2 + 1], dl[i * 2 + 1]);
            }
        }
        __syncthreads();

#pragma unroll
        for (int kk = 0; kk < 4; kk++) {
            uint4 Ah, Al;
            ldsm4(Ah, aA + kk * 32);
            ldsm4(Al, aAl + kk * 32);
#pragma unroll
            for (int jp = 0; jp < 4; jp++) {
                uint4 Bh, Bl;
                ldsm4(Bh, aW + (jp * 16 * SQ) * 4 + kk * 32);
                ldsm4(Bl, aWl + (jp * 16 * SQ) * 4 + kk * 32);
                MMA4(S[2 * jp],     Ah, Bh.x, Bh.z);
                MMA4(S[2 * jp],     Ah, Bl.x, Bl.z);
                MMA4(S[2 * jp],     Al, Bh.x, Bh.z);
                MMA4(S[2 * jp + 1], Ah, Bh.y, Bh.w);
                MMA4(S[2 * jp + 1], Ah, Bl.y, Bl.w);
                MMA4(S[2 * jp + 1], Al, Bh.y, Bh.w);
            }
        }
    }

    const int fr = lane >> 2, fc = lane & 3;
    const int r0 = m0 + warp * 16 + fr;
    const int r1 = r0 + 8;
#pragma unroll
    for (int j = 0; j < 8; j++) {
        int col = n0 + j * 8 + fc * 2;
        float v0 = S[j][0], v1 = S[j][1], v2 = S[j][2], v3 = S[j][3];
        if (bng) {
            float s0 = bng[col] * rsqrtf(bnv[col] + 1e-5f);
            float s1 = bng[col + 1] * rsqrtf(bnv[col + 1] + 1e-5f);
            float b0 = bnb[col] - bnm[col] * s0;
            float b1 = bnb[col + 1] - bnm[col + 1] * s1;
            v0 = v0 * s0 + b0; v1 = v1 * s1 + b1;
            v2 = v2 * s0 + b0; v3 = v3 * s1 + b1;
        }
        *(float2*)(Cf + (size_t)r0 * N + col) = make_float2(v0, v1);
        *(float2*)(Cf + (size_t)r1 * N + col) = make_float2(v2, v3);
        if (C2 && col < c2cols) {
            *(float2*)(C2 + (size_t)r0 * c2cols + col) = make_float2(v0, v1);
            *(float2*)(C2 + (size_t)r1 * c2cols + col) = make_float2(v2, v3);
        }
    }
}

// ============ fused QKV projection (single launch, grid.z selects) =========
// Epilogue writes plain fp16 pairs (pure-fp16 attention).
__global__ void __launch_bounds__(256) gemm_qkv(
    const float* __restrict__ A,
    const float* __restrict__ Wq, const float* __restrict__ Wk, const float* __restrict__ Wv,
    unsigned* __restrict__ Qh, unsigned* __restrict__ Kh, unsigned* __restrict__ Vh)
{
    extern __shared__ unsigned gsm[];
    unsigned* AhS = gsm;
    unsigned* AlS = gsm + 128 * SQ;
    unsigned* WhS = gsm + 256 * SQ;
    unsigned* WlS = gsm + 320 * SQ;

    const int tid = threadIdx.x, lane = tid & 31, warp = tid >> 5;
    const int m0 = blockIdx.y * 128, n0 = blockIdx.x * 64;
    const int z = blockIdx.z;
    const float* W = (z == 0) ? Wq : (z == 1) ? Wk : Wv;
    unsigned* Chi = (z == 0) ? Qh : (z == 1) ? Kh : Vh;
    const float mult = (z == 0) ? 1.4426950408889634f : 1.0f;
    const int K = C4, N = CIN;

    const unsigned sb = smem_u32(gsm);
    const unsigned laneoff =
        (((lane & 7) + ((lane >> 3) & 1) * 8) * SQ + (lane >> 4) * 4) * 4;
    const unsigned aA = sb + (warp * 16 * SQ) * 4 + laneoff;
    const unsigned aAl = aA + 128 * SQ * 4;
    const unsigned aW = sb + (256 * SQ) * 4 + laneoff;
    const unsigned aWl = aW + 64 * SQ * 4;

    float S[8][4] = {};

    {
        int row = tid >> 1, half = tid & 1;
        const float* src = A + (size_t)(m0 + row) * K + half * 32;
        unsigned* dh = AhS + row * SQ + half * 16;
        unsigned* dl = AlS + row * SQ + half * 16;
#pragma unroll
        for (int i = 0; i < 8; i++) {
            float4 v = *(const float4*)(src + i * 4);
            split_pair(v.x, v.y, dh[i * 2], dl[i * 2]);
            split_pair(v.z, v.w, dh[i * 2 + 1], dl[i * 2 + 1]);
        }
    }
    {
        int row = tid >> 2, q = tid & 3;
        const float* src = W + (size_t)(n0 + row) * K + q * 16;
        unsigned* dh = WhS + row * SQ + q * 8;
        unsigned* dl = WlS + row * SQ + q * 8;
#pragma unroll
        for (int i = 0; i < 4; i++) {
            float4 v = *(const float4*)(src + i * 4);
            split_pair(v.x, v.y, dh[i * 2], dl[i * 2]);
            split_pair(v.z, v.w, dh[i * 2 + 1], dl[i * 2 + 1]);
        }
    }
    __syncthreads();

#pragma unroll
    for (int kk = 0; kk < 4; kk++) {
        uint4 Ah, Al;
        ldsm4(Ah, aA + kk * 32);
        ldsm4(Al, aAl + kk * 32);
#pragma unroll
        for (int jp = 0; jp < 4; jp++) {
            uint4 Bh, Bl;
            ldsm4(Bh, aW + (jp * 16 * SQ) * 4 + kk * 32);
            ldsm4(Bl, aWl + (jp * 16 * SQ) * 4 + kk * 32);
            MMA4(S[2 * jp],     Ah, Bh.x, Bh.z);
            MMA4(S[2 * jp],     Ah, Bl.x, Bl.z);
            MMA4(S[2 * jp],     Al, Bh.x, Bh.z);
            MMA4(S[2 * jp + 1], Ah, Bh.y, Bh.w);
            MMA4(S[2 * jp + 1], Ah, Bl.y, Bl.w);
            MMA4(S[2 * jp + 1], Al, Bh.y, Bh.w);
        }
    }

    const int fr = lane >> 2, fc = lane & 3;
    const int r0 = m0 + warp * 16 + fr;
    const int r1 = r0 + 8;
#pragma unroll
    for (int j = 0; j < 8; j++) {
        int col = n0 + j * 8 + fc * 2;
        int ci = col >> 1, nw = N >> 1;
        Chi[(size_t)r0 * nw + ci] = pack2h(S[j][0] * mult, S[j][1] * mult);
        Chi[(size_t)r1 * nw + ci] = pack2h(S[j][2] * mult, S[j][3] * mult);
    }
}

// ============ fused depthwise 3x3 + pointwise 1x1 + BN2 (8-token blocks) ===
__global__ void __launch_bounds__(256) dwpw8(
    const float* __restrict__ ident, const float* __restrict__ Rprev,
    const float* __restrict__ dw, const float* __restrict__ pw,
    const float* __restrict__ bn2g, const float* __restrict__ bn2b,
    const float* __restrict__ bn2m, const float* __restrict__ bn2v,
    float* __restrict__ Rout, int s)
{
    __shared__ float Ws[64 * 65];
    __shared__ float Ds[8 * 68];
    __shared__ float wsm[C4 * 9];
    const int tid = threadIdx.x;

#pragma unroll
    for (int k = 0; k < 16; k++) {
        int idx = tid + k * 256;
        int oo = idx >> 6, cc = idx & 63;
        Ws[cc * 65 + oo] = pw[idx];
    }
    for (int i = tid; i < C4 * 9; i += 256) wsm[i] = dw[i];
    __syncthreads();

    const int lt = tid >> 5;
    const int ol = tid & 31;
    const int g = blockIdx.x * 8 + lt;
    const int b = g / T_TOK, t = g - b * T_TOK;
    const int hh = t / WW, ww = t % WW;

    {
        const float* ib = ident + (size_t)b * T_TOK * CIN + s * C4;
        const float* rb = Rprev ? (Rprev + (size_t)b * T_TOK * C4) : nullptr;
        float a0 = 0.f, a1 = 0.f;
        const int c0 = ol, c1 = ol + 32;
#pragma unroll
        for (int kh = 0; kh < 3; kh++) {
            int h2 = hh + kh - 1;
            if ((unsigned)h2 >= HH) continue;
#pragma unroll
            for (int kw = 0; kw < 3; kw++) {
                int w2 = ww + kw - 1;
                if ((unsigned)w2 >= WW) continue;
                int tt = h2 * WW + w2;
                float v0 = ib[(size_t)tt * CIN + c0];
                float v1 = ib[(size_t)tt * CIN + c1];
                if (rb) {
                    v0 += rb[(size_t)tt * C4 + c0];
                    v1 += rb[(size_t)tt * C4 + c1];
                }
                a0 += v0 * wsm[c0 * 9 + kh * 3 + kw];
                a1 += v1 * wsm[c1 * 9 + kh * 3 + kw];
            }
        }
        Ds[lt * 68 + c0] = a0;
        Ds[lt * 68 + c1] = a1;
    }
    __syncthreads();

    float acc0 = 0.f, acc1 = 0.f;
#pragma unroll 16
    for (int c = 0; c < 64; c++) {
        float d = Ds[lt * 68 + c];
        acc0 += d * Ws[c * 65 + ol];
        acc1 += d * Ws[c * 65 + ol + 32];
    }
    {
        float sc0 = bn2g[ol] * rsqrtf(bn2v[ol] + 1e-5f);
        float bi0 = bn2b[ol] - bn2m[ol] * sc0;
        float sc1 = bn2g[ol + 32] * rsqrtf(bn2v[ol + 32] + 1e-5f);
        float bi1 = bn2b[ol + 32] - bn2m[ol + 32] * sc1;
        Rout[(size_t)g * C4 + ol]      = acc0 * sc0 + bi0;
        Rout[(size_t)g * C4 + ol + 32] = acc1 * sc1 + bi1;
    }
}

// ================= pure fp16 tensor-core flash attention ===================
// 8 warps, Q-tile 128, K-tile 64; cp.async double-buffered K/V.
// Pure fp16: S = Qh*Kh, O = Ph*Vh (no split terms).
// Fixed-max softmax (Q pre-scaled by log2e -> ex2); V via ldmatrix.trans.
// smem u32: Qh[0..4608), stage st at 4608+st*4608: Kh+0, Vh+2304
#define AT_SMEM (13824 * 4)    // 55296 B -> 2 CTAs/SM (and well under limits)
__global__ void __launch_bounds__(256, 2) attn7(
    const unsigned* __restrict__ Qhg,
    const unsigned* __restrict__ Khg,
    const unsigned* __restrict__ Vhg,
    float* __restrict__ O)
{
    extern __shared__ unsigned smu[];
    unsigned* QhS = smu;

    const int tid = threadIdx.x, lane = tid & 31, warp = tid >> 5;
    const int y = blockIdx.y;
    const int s = y >> 3, b = (y >> 2) & 1, h = y & 3;
    const int t0 = blockIdx.x * 128;
    const size_t row0 = (size_t)(s * NB + b) * T_TOK;

    const unsigned sb = smem_u32(smu);
    const unsigned laneoff =
        (((lane & 7) + ((lane >> 3) & 1) * 8) * SQ + (lane >> 4) * 4) * 4;

    // ---- stage Q (once) ----
    {
        int row = tid >> 1, off = (tid & 1) * 16;
        const uint4* sH = (const uint4*)(Qhg + (row0 + t0 + row) * 128 + h * 32 + off);
        uint4* dH = (uint4*)(QhS + row * SQ + off);
#pragma unroll
        for (int i = 0; i < 4; i++) dH[i] = sH[i];
    }

    const int fr = lane >> 2, fc = lane & 3;
    const int qr = warp * 16 + fr;

    const unsigned aQh = sb + (warp * 16 * SQ) * 4 + laneoff;

    const int srow = tid >> 2, soff = (tid & 3) * 8;
    auto issue_stage = [&](int st, int kb) {
        size_t kg = (row0 + (size_t)kb * 64 + srow) * 128 + h * 32 + soff;
        unsigned base = sb + (4608 + st * 4608 + srow * SQ + soff) * 4;
        cpasync16(base,                 Khg + kg);
        cpasync16(base + 16,            Khg + kg + 4);
        cpasync16(base + 2304 * 4,      Vhg + kg);
        cpasync16(base + 2304 * 4 + 16, Vhg + kg + 4);
    };

    float Ov[8][4] = {};
    float l0s = 0.f, l1s = 0.f;

    issue_stage(0, 0);
    asm volatile("cp.async.commit_group;");

    for (int kb = 0; kb < T_TOK / 64; kb++) {
        const int cur = kb & 1;
        if (kb + 1 < T_TOK / 64) {
            issue_stage(cur ^ 1, kb + 1);
            asm volatile("cp.async.commit_group;");
            asm volatile("cp.async.wait_group 1;");
        } else {
            asm volatile("cp.async.wait_group 0;");
        }
        __syncthreads();

        const unsigned bstg = sb + (4608 + cur * 4608) * 4 + laneoff;
        const unsigned aKh = bstg;
        const unsigned aVh = bstg + 2304 * 4;

        // ---- S = Qh Kh^T : 16x64 per warp ----
        float S[8][4];
#pragma unroll
        for (int j = 0; j < 8; j++)
            S[j][0] = S[j][1] = S[j][2] = S[j][3] = 0.f;

#pragma unroll
        for (int kk = 0; kk < 4; kk++) {
            uint4 Ah;
            ldsm4(Ah, aQh + kk * 32);
#pragma unroll
            for (int jp = 0; jp < 4; jp++) {
                uint4 Bh;
                ldsm4(Bh, aKh + (jp * 16 * SQ) * 4 + kk * 32);
                MMA4H(S[2 * jp],     Ah, Bh.x, Bh.z);
                MMA4H(S[2 * jp + 1], Ah, Bh.y, Bh.w);
            }
        }

        // ---- softmax (fixed max 0; ex2) + fp16 P + PV ----
#pragma unroll
        for (int kk = 0; kk < 4; kk++) {
            const int j0 = 2 * kk, j1 = 2 * kk + 1;
            float p00 = fexp2(S[j0][0]), p01 = fexp2(S[j0][1]);
            float p02 = fexp2(S[j0][2]), p03 = fexp2(S[j0][3]);
            float p10 = fexp2(S[j1][0]), p11 = fexp2(S[j1][1]);
            float p12 = fexp2(S[j1][2]), p13 = fexp2(S[j1][3]);
            l0s += (p00 + p01) + (p10 + p11);
            l1s += (p02 + p03) + (p12 + p13);
            uint4 Ph;
            Ph.x = pack2h(p00, p01);
            Ph.y = pack2h(p02, p03);
            Ph.z = pack2h(p10, p11);
            Ph.w = pack2h(p12, p13);
#pragma unroll
            for (int jp = 0; jp < 4; jp++) {
                uint4 Bh;
                ldsm4t(Bh, aVh + (kk * 16 * SQ) * 4 + jp * 32);
                MMA4H(Ov[2 * jp],     Ph, Bh.x, Bh.y);
                MMA4H(Ov[2 * jp + 1], Ph, Bh.z, Bh.w);
            }
        }
        __syncthreads();
    }

    // ---- epilogue: reduce l over the quad, normalize, store ----
    l0s += __shfl_xor_sync(0xffffffffu, l0s, 1);
    l0s += __shfl_xor_sync(0xffffffffu, l0s, 2);
    l1s += __shfl_xor_sync(0xffffffffu, l1s, 1);
    l1s += __shfl_xor_sync(0xffffffffu, l1s, 2);
    float inv0 = 1.0f / l0s, inv1 = 1.0f / l1s;
    const size_t feat0 = (size_t)s * CIN + h * DH;
    const size_t r0g = (size_t)b * T_TOK + t0 + qr;
    const size_t r1g = r0g + 8;
#pragma unroll
    for (int j = 0; j < 8; j++) {
        size_t col = feat0 + j * 8 + fc * 2;
        *(float2*)(O + r0g * (4 * CIN) + col) = make_float2(Ov[j][0] * inv0, Ov[j][1] * inv0);
        *(float2*)(O + r1g * (4 * CIN) + col) = make_float2(Ov[j][2] * inv1, Ov[j][3] * inv1);
    }
}

// ---------------------------------------------------------------------------
extern "C" void kernel_launch(void* const* d_in, const int* in_sizes, int n_in,
                              void* d_out, int out_size)
{
    const float* x    = (const float*)d_in[0];
    const float* w1   = (const float*)d_in[1];
    const float* bn1g = (const float*)d_in[2];
    const float* bn1b = (const float*)d_in[3];
    const float* bn1m = (const float*)d_in[4];
    const float* bn1v = (const float*)d_in[5];
    const float* dww  = (const float*)d_in[6];
    const float* pww  = (const float*)d_in[7];
    const float* bn2g = (const float*)d_in[8];
    const float* bn2b = (const float*)d_in[9];
    const float* bn2m = (const float*)d_in[10];
    const float* bn2v = (const float*)d_in[11];
    const float* Wq   = (const float*)d_in[12];
    const float* Wk   = (const float*)d_in[13];
    const float* Wv   = (const float*)d_in[14];
    const float* Wout = (const float*)d_in[15];
    float* out = (float*)d_out;

    void* p;
    cudaGetSymbolAddress(&p, g_identity); float* ident = (float*)p;
    cudaGetSymbolAddress(&p, g_R);        float* Rp    = (float*)p;
    cudaGetSymbolAddress(&p, g_O);        float* Op    = (float*)p;
    cudaGetSymbolAddress(&p, g_Qh);  unsigned* Qh = (unsigned*)p;
    cudaGetSymbolAddress(&p, g_Kh);  unsigned* Kh = (unsigned*)p;
    cudaGetSymbolAddress(&p, g_Vh);  unsigned* Vh = (unsigned*)p;

    cudaFuncSetAttribute(gemm_mma, cudaFuncAttributeMaxDynamicSharedMemorySize, GEMM_SMEM);
    cudaFuncSetAttribute(gemm_qkv, cudaFuncAttributeMaxDynamicSharedMemorySize, GEMM_SMEM);
    cudaFuncSetAttribute(attn7, cudaFuncAttributeMaxDynamicSharedMemorySize, AT_SMEM);

    // [0] conv_in + BN1 (inline) -> identity ; channels [0,64) also into R[0]
    gemm_mma<<<dim3(4, 36), 256, GEMM_SMEM>>>(
        x, w1, NB * T_TOK, CIN, CIN, ident, bn1g, bn1b, bn1m, bn1v, Rp, C4);

    // [1..3] Res2Net scales (fused dw+pw+BN2, 8-token blocks, grid 576)
    for (int s = 1; s <= 3; s++) {
        const float* prev = (s == 1) ? nullptr : (Rp + (size_t)(s - 1) * NB * T_TOK * C4);
        dwpw8<<<(NB * T_TOK) / 8, 256>>>(
            ident, prev, dww, pww, bn2g, bn2b, bn2m, bn2v,
            Rp + (size_t)s * NB * T_TOK * C4, s);
    }

    // [4] fused Q/K/V projections -> fp16 (Q scaled by log2e)
    gemm_qkv<<<dim3(4, 144, 3), 256, GEMM_SMEM>>>(
        Rp, Wq, Wk, Wv, Qh, Kh, Vh);

    // [5] pure fp16 flash attention
    attn7<<<dim3(T_TOK / 128, NS * NB * NH), 256, AT_SMEM>>>(
        Qh, Kh, Vh, Op);

    // [6] output projection -> d_out
    gemm_mma<<<dim3(4, 36), 256, GEMM_SMEM>>>(
        Op, Wout, NB * T_TOK, CIN, 4 * CIN, out,
        nullptr, nullptr, nullptr, nullptr, nullptr, 0);
}